// round 15
// baseline (speedup 1.0000x reference)
#include <cuda_runtime.h>
#include <cuda_bf16.h>
#include <math.h>
#include <stdint.h>

// ---------------------------------------------------------------------------
// Problem constants
// ---------------------------------------------------------------------------
#define BATCH   8
#define HH      128
#define WW_     128
#define LL      (HH*WW_)
#define CC      192
#define HEADS   6
#define HD      32
#define WS      8
#define NWIN    64
#define SHIFT   4
#define HIDDEN  768
#define MROWS   (BATCH*LL)                 // 131072
#define NWINDOWS (BATCH*(HH/WS)*(WW_/WS))  // 2048
#define POS_DIM 12
#define POS_TAB 225
#define QSCALE  0.17677669529663687f

// ---------------------------------------------------------------------------
// Device scratch
// ---------------------------------------------------------------------------
__device__ __nv_bfloat16 gb_qkv[(size_t)MROWS * 3 * CC];
__device__ __nv_bfloat16 gb_attn[(size_t)MROWS * CC];
__device__ __nv_bfloat16 gb_ln2[(size_t)MROWS * CC];
__device__ __nv_bfloat16 gb_hid[(size_t)MROWS * HIDDEN];
__device__ float g_bias[4 * HEADS * NWIN * NWIN];
__device__ __nv_bfloat16 gb_wt_qkv[3 * CC * CC];
__device__ __nv_bfloat16 gb_wt_proj[CC * CC];
__device__ __nv_bfloat16 gb_wt_fc1[HIDDEN * CC];
__device__ __nv_bfloat16 gb_wt_fc2[CC * HIDDEN];

// ---------------------------------------------------------------------------
// Helpers
// ---------------------------------------------------------------------------
__device__ __forceinline__ uint32_t smem_u32(const void* p) {
    uint32_t a;
    asm("{ .reg .u64 t; cvta.to.shared.u64 t, %1; cvt.u32.u64 %0, t; }" : "=r"(a) : "l"(p));
    return a;
}
__device__ __forceinline__ void cpasync16(uint32_t s, const void* g) {
    asm volatile("cp.async.cg.shared.global [%0], [%1], 16;" :: "r"(s), "l"(g));
}
__device__ __forceinline__ void cp_commit() {
    asm volatile("cp.async.commit_group;" ::: "memory");
}
__device__ __forceinline__ void cp_wait1() {
    asm volatile("cp.async.wait_group 1;" ::: "memory");
}
__device__ __forceinline__ void ldsm_x4(uint32_t addr, uint32_t* r) {
    asm volatile("ldmatrix.sync.aligned.m8n8.x4.shared.b16 {%0,%1,%2,%3}, [%4];"
                 : "=r"(r[0]), "=r"(r[1]), "=r"(r[2]), "=r"(r[3]) : "r"(addr));
}
__device__ __forceinline__ void mma_bf16(float* d, const uint32_t* a, const uint32_t* b) {
    asm volatile(
        "mma.sync.aligned.m16n8k16.row.col.f32.bf16.bf16.f32 "
        "{%0,%1,%2,%3}, {%4,%5,%6,%7}, {%8,%9}, {%0,%1,%2,%3};"
        : "+f"(d[0]), "+f"(d[1]), "+f"(d[2]), "+f"(d[3])
        : "r"(a[0]), "r"(a[1]), "r"(a[2]), "r"(a[3]), "r"(b[0]), "r"(b[1]));
}
__device__ __forceinline__ uint32_t packbf2(float x, float y) {
    __nv_bfloat162 t = __float22bfloat162_rn(make_float2(x, y));
    return *(uint32_t*)&t;
}
__device__ __forceinline__ float gelu_exact(float x) {
    return 0.5f * x * (1.0f + erff(x * 0.7071067811865476f));
}

// ---------------------------------------------------------------------------
// Combined weight transpose
// ---------------------------------------------------------------------------
#define TW_QKV (3*CC*CC)
#define TW_PROJ (CC*CC)
#define TW_FC1 (CC*HIDDEN)
#define TW_FC2 (HIDDEN*CC)
#define TW_TOTAL (TW_QKV + TW_PROJ + TW_FC1 + TW_FC2)

__global__ void transpose_all(const float* __restrict__ qkv_w, const float* __restrict__ proj_w,
                              const float* __restrict__ fc1_w, const float* __restrict__ fc2_w) {
    int i = blockIdx.x * 256 + threadIdx.x;
    if (i >= TW_TOTAL) return;
    const float* w; __nv_bfloat16* wt; int K, N, off;
    if (i < TW_QKV) { w = qkv_w; wt = gb_wt_qkv; K = CC; N = 3 * CC; off = i; }
    else if (i < TW_QKV + TW_PROJ) { w = proj_w; wt = gb_wt_proj; K = CC; N = CC; off = i - TW_QKV; }
    else if (i < TW_QKV + TW_PROJ + TW_FC1) { w = fc1_w; wt = gb_wt_fc1; K = CC; N = HIDDEN; off = i - TW_QKV - TW_PROJ; }
    else { w = fc2_w; wt = gb_wt_fc2; K = HIDDEN; N = CC; off = i - TW_QKV - TW_PROJ - TW_FC1; }
    int k = off / N, n = off % N;
    wt[(size_t)n * K + k] = __float2bfloat16(w[off]);
}

// ---------------------------------------------------------------------------
// Bias table with inline position-MLP
// ---------------------------------------------------------------------------
__device__ __forceinline__ void ln_relu12(const float* p, float* q,
                                          const float* g, const float* b) {
    float s = 0.f, s2 = 0.f;
#pragma unroll
    for (int i = 0; i < POS_DIM; i++) { s += p[i]; s2 += p[i] * p[i]; }
    float mu = s / 12.0f;
    float var = s2 / 12.0f - mu * mu;
    float rs = rsqrtf(var + 1e-5f);
#pragma unroll
    for (int i = 0; i < POS_DIM; i++) q[i] = fmaxf((p[i] - mu) * rs * g[i] + b[i], 0.0f);
}

__global__ void bias_build(
    const float* __restrict__ pp_w, const float* __restrict__ pp_b,
    const float* __restrict__ p1_g, const float* __restrict__ p1_b,
    const float* __restrict__ p1_w, const float* __restrict__ p1_bias,
    const float* __restrict__ p2_g, const float* __restrict__ p2_b,
    const float* __restrict__ p2_w, const float* __restrict__ p2_bias,
    const float* __restrict__ p3_g, const float* __restrict__ p3_b,
    const float* __restrict__ p3_w, const float* __restrict__ p3_bias) {
    int idx = blockIdx.x * 256 + threadIdx.x;
    if (idx >= 4 * HEADS * NWIN * NWIN) return;
    int j = idx & 63;
    int r = (idx >> 6) & 63;
    int h = (idx >> 12) % HEADS;
    int t = idx / (HEADS * NWIN * NWIN);
    int ry = r >> 3, rx = r & 7, jy = j >> 3, jx = j & 7;

    float bh = (float)(ry - jy), bw = (float)(rx - jx);
    float p[POS_DIM], q[POS_DIM];
#pragma unroll
    for (int k = 0; k < POS_DIM; k++) p[k] = bh * pp_w[k] + bw * pp_w[POS_DIM + k] + pp_b[k];
    ln_relu12(p, q, p1_g, p1_b);
#pragma unroll
    for (int k = 0; k < POS_DIM; k++) {
        float s = p1_bias[k];
#pragma unroll
        for (int i = 0; i < POS_DIM; i++) s += q[i] * p1_w[i * POS_DIM + k];
        p[k] = s;
    }
    ln_relu12(p, q, p2_g, p2_b);
#pragma unroll
    for (int k = 0; k < POS_DIM; k++) {
        float s = p2_bias[k];
#pragma unroll
        for (int i = 0; i < POS_DIM; i++) s += q[i] * p2_w[i * POS_DIM + k];
        p[k] = s;
    }
    ln_relu12(p, q, p3_g, p3_b);
    float bias = p3_bias[h];
#pragma unroll
    for (int i = 0; i < POS_DIM; i++) bias += q[i] * p3_w[i * HEADS + h];

    int lhr = (t & 2) ? (ry < (WS - SHIFT) ? 1 : 2) : 0;
    int lhj = (t & 2) ? (jy < (WS - SHIFT) ? 1 : 2) : 0;
    int lwr = (t & 1) ? (rx < (WS - SHIFT) ? 1 : 2) : 0;
    int lwj = (t & 1) ? (jx < (WS - SHIFT) ? 1 : 2) : 0;
    if (lhr != lhj || lwr != lwj) bias -= 100.0f;
    g_bias[idx] = bias;
}

#define CH_PER_BUF (192 * 8)
#define A_CHB  (128 * 8)
#define B_CHB  (64 * 8)
#define ABYTES (3 * A_CHB * 16)
#define BBYTES (3 * B_CHB * 16)
#define KM_SMEM (ABYTES + 2 * BBYTES)

// ---------------------------------------------------------------------------
// Fused LN1 + QKV GEMM (multi-N, A resident). One CTA owns 128 rows:
// B tiles prefetched via cp.async FIRST, then warp-per-row LN1 (x gathered
// via shift+window map, fp32) written bf16 directly into swizzled A smem.
// EPI: +bias, Q-scale cols<192 -> bf16.
// ---------------------------------------------------------------------------
__global__ void __launch_bounds__(256) gemm_ln1_qkv(
    const float* __restrict__ x, const __nv_bfloat16* __restrict__ BT,
    const float* __restrict__ gamma, const float* __restrict__ beta,
    const float* __restrict__ bias, __nv_bfloat16* __restrict__ out) {
    extern __shared__ __align__(16) uint4 kmsq[];
    uint32_t sbase = smem_u32(kmsq);
    char* smem_c = (char*)kmsq;
    const int NOUT = 576;
    const int NT = 9;
    int tid = threadIdx.x;
    int wid = tid >> 5, lane = tid & 31;
    int wm = wid & 3, wn = wid >> 2;
    int m0 = blockIdx.x * 128;

    int b_row = tid >> 2;
    int b_ch0 = (tid & 3) * 2;

    int l15 = lane & 15, lhi = lane >> 4;
    int a_lrow = wm * 32 + l15;
    int a_sw = l15 & 7;
    int b_lrow = wn * 32 + (lhi << 3) + (lane & 7);
    int b_sw = lane & 7;
    int b_chlo = (lane >> 3) & 1;

    // prologue: B tiles 0,1 FIRST (overlap with LN below)
#pragma unroll
    for (int bt = 0; bt < 2; bt++) {
        const __nv_bfloat16* Bb = BT + (size_t)bt * 64 * CC;
        uint32_t base = sbase + ABYTES + bt * BBYTES;
#pragma unroll
        for (int kc = 0; kc < 3; kc++) {
            uint32_t dst = base + kc * B_CHB * 16;
            int k0 = kc << 6;
#pragma unroll
            for (int i = 0; i < 2; i++) {
                int ch = b_ch0 + i;
                cpasync16(dst + (b_row * 8 + (ch ^ (b_row & 7))) * 16,
                          Bb + (size_t)b_row * CC + k0 + ch * 8);
            }
        }
        cp_commit();
    }

    // LN1 into A smem: warp handles rows wid*16 .. +15, lane strided cols
    for (int rr = 0; rr < 16; rr++) {
        int r = wid * 16 + rr;
        int g = m0 + r;
        int bb = g >> 14, rem = g & 16383;
        int win = rem >> 6, rloc = rem & 63;
        int wy = win >> 4, wx = win & 15, ryy = rloc >> 3, rxx = rloc & 7;
        int hh = (wy * WS + ryy + SHIFT) & 127;
        int ww = (wx * WS + rxx + SHIFT) & 127;
        const float* p = x + ((size_t)bb * LL + hh * WW_ + ww) * CC;
        float v[6], s = 0.f, s2 = 0.f;
#pragma unroll
        for (int k = 0; k < 6; k++) {
            v[k] = p[lane + 32 * k];
            s += v[k]; s2 += v[k] * v[k];
        }
#pragma unroll
        for (int o = 16; o > 0; o >>= 1) {
            s += __shfl_xor_sync(0xFFFFFFFFu, s, o);
            s2 += __shfl_xor_sync(0xFFFFFFFFu, s2, o);
        }
        float mu = s * (1.0f / 192.0f);
        float rs = rsqrtf(s2 * (1.0f / 192.0f) - mu * mu + 1e-5f);
        int rsw = (r & 7);
#pragma unroll
        for (int k = 0; k < 6; k++) {
            int c = lane + 32 * k;
            float o = (v[k] - mu) * rs * gamma[c] + beta[c];
            int kc = c >> 6, c8 = (c >> 3) & 7, byt = (c & 7) * 2;
            *(__nv_bfloat16*)(smem_c + kc * (A_CHB * 16) +
                              (r * 8 + (c8 ^ rsw)) * 16 + byt) = __float2bfloat16(o);
        }
    }

    for (int nt = 0; nt < NT; nt++) {
        cp_wait1();
        __syncthreads();   // orders LN A-writes (first iter) + B buffer ready

        float acc[2][4][4];
#pragma unroll
        for (int i = 0; i < 2; i++)
#pragma unroll
            for (int j = 0; j < 4; j++)
#pragma unroll
                for (int k = 0; k < 4; k++) acc[i][j][k] = 0.f;

        uint32_t bbase = sbase + ABYTES + (nt & 1) * BBYTES;
#pragma unroll
        for (int kc = 0; kc < 3; kc++) {
            uint32_t abuf = sbase + kc * A_CHB * 16;
            uint32_t bbuf = bbase + kc * B_CHB * 16;
#pragma unroll
            for (int ks = 0; ks < 4; ks++) {
                uint32_t a[2][4], b[2][4];
                int achk = 2 * ks + lhi;
#pragma unroll
                for (int mt = 0; mt < 2; mt++) {
                    uint32_t idx = (a_lrow + mt * 16) * 8 + (achk ^ a_sw);
                    ldsm_x4(abuf + idx * 16, a[mt]);
                }
                int bchk = 2 * ks + b_chlo;
#pragma unroll
                for (int nt16 = 0; nt16 < 2; nt16++) {
                    uint32_t idx = (b_lrow + nt16 * 16) * 8 + (bchk ^ b_sw);
                    ldsm_x4(bbuf + idx * 16, b[nt16]);
                }
#pragma unroll
                for (int mt = 0; mt < 2; mt++) {
#pragma unroll
                    for (int nt16 = 0; nt16 < 2; nt16++) {
                        mma_bf16(acc[mt][nt16 * 2 + 0], a[mt], &b[nt16][0]);
                        mma_bf16(acc[mt][nt16 * 2 + 1], a[mt], &b[nt16][2]);
                    }
                }
            }
        }
        __syncthreads();

        if (nt + 2 < NT) {
            const __nv_bfloat16* Bb = BT + (size_t)(nt + 2) * 64 * CC;
            uint32_t dst0 = sbase + ABYTES + (nt & 1) * BBYTES;
#pragma unroll
            for (int kc = 0; kc < 3; kc++) {
                uint32_t dst = dst0 + kc * B_CHB * 16;
                int k0 = kc << 6;
#pragma unroll
                for (int i = 0; i < 2; i++) {
                    int ch = b_ch0 + i;
                    cpasync16(dst + (b_row * 8 + (ch ^ (b_row & 7))) * 16,
                              Bb + (size_t)b_row * CC + k0 + ch * 8);
                }
            }
        }
        cp_commit();

        int n0 = nt * 64;
#pragma unroll
        for (int mt = 0; mt < 2; mt++) {
            int g0 = m0 + wm * 32 + mt * 16 + (lane >> 2);
            int g1 = g0 + 8;
            size_t ob0 = (size_t)g0 * NOUT;
            size_t ob1 = (size_t)g1 * NOUT;
#pragma unroll
            for (int ne = 0; ne < 4; ne++) {
                int col = n0 + wn * 32 + ne * 8 + 2 * (lane & 3);
                float b0 = bias[col], b1 = bias[col + 1];
                float2 v0 = make_float2(acc[mt][ne][0] + b0, acc[mt][ne][1] + b1);
                float2 v1 = make_float2(acc[mt][ne][2] + b0, acc[mt][ne][3] + b1);
                float sc = (col < CC) ? QSCALE : 1.0f;
                v0.x *= sc; v0.y *= sc; v1.x *= sc; v1.y *= sc;
                *(__nv_bfloat162*)(out + ob0 + col) = __float22bfloat162_rn(v0);
                *(__nv_bfloat162*)(out + ob1 + col) = __float22bfloat162_rn(v1);
            }
        }
    }
}

// ---------------------------------------------------------------------------
// K=192 multi-N GEMM (round-14): used for FC1. A resident, B double-buffered.
// EPI: gelu(+bias) -> bf16
// ---------------------------------------------------------------------------
__global__ void __launch_bounds__(256) gemm_k192_multi(
    const __nv_bfloat16* __restrict__ A, const __nv_bfloat16* __restrict__ BT,
    const float* __restrict__ bias, __nv_bfloat16* __restrict__ out, int NOUT) {
    extern __shared__ __align__(16) uint4 kmsq[];
    uint32_t sbase = smem_u32(kmsq);
    int tid = threadIdx.x;
    int wid = tid >> 5, lane = tid & 31;
    int wm = wid & 3, wn = wid >> 2;
    int m0 = blockIdx.x * 128;
    const int NT = NOUT >> 6;
    const __nv_bfloat16* Ab = A + (size_t)m0 * CC;

    int a_row = tid >> 1;
    int a_ch0 = (tid & 1) * 4;
    int b_row = tid >> 2;
    int b_ch0 = (tid & 3) * 2;

    int l15 = lane & 15, lhi = lane >> 4;
    int a_lrow = wm * 32 + l15;
    int a_sw = l15 & 7;
    int b_lrow = wn * 32 + (lhi << 3) + (lane & 7);
    int b_sw = lane & 7;
    int b_chlo = (lane >> 3) & 1;

#pragma unroll
    for (int kc = 0; kc < 3; kc++) {
        uint32_t dst = sbase + kc * A_CHB * 16;
        int k0 = kc << 6;
#pragma unroll
        for (int i = 0; i < 4; i++) {
            int ch = a_ch0 + i;
            cpasync16(dst + (a_row * 8 + (ch ^ (a_row & 7))) * 16,
                      Ab + (size_t)a_row * CC + k0 + ch * 8);
        }
    }
    {
        const __nv_bfloat16* Bb = BT;
#pragma unroll
        for (int kc = 0; kc < 3; kc++) {
            uint32_t dst = sbase + ABYTES + kc * B_CHB * 16;
            int k0 = kc << 6;
#pragma unroll
            for (int i = 0; i < 2; i++) {
                int ch = b_ch0 + i;
                cpasync16(dst + (b_row * 8 + (ch ^ (b_row & 7))) * 16,
                          Bb + (size_t)b_row * CC + k0 + ch * 8);
            }
        }
        cp_commit();
    }
    {
        const __nv_bfloat16* Bb = BT + (size_t)64 * CC;
#pragma unroll
        for (int kc = 0; kc < 3; kc++) {
            uint32_t dst = sbase + ABYTES + BBYTES + kc * B_CHB * 16;
            int k0 = kc << 6;
#pragma unroll
            for (int i = 0; i < 2; i++) {
                int ch = b_ch0 + i;
                cpasync16(dst + (b_row * 8 + (ch ^ (b_row & 7))) * 16,
                          Bb + (size_t)b_row * CC + k0 + ch * 8);
            }
        }
        cp_commit();
    }

    for (int nt = 0; nt < NT; nt++) {
        cp_wait1();
        __syncthreads();

        float acc[2][4][4];
#pragma unroll
        for (int i = 0; i < 2; i++)
#pragma unroll
            for (int j = 0; j < 4; j++)
#pragma unroll
                for (int k = 0; k < 4; k++) acc[i][j][k] = 0.f;

        uint32_t bbase = sbase + ABYTES + (nt & 1) * BBYTES;
#pragma unroll
        for (int kc = 0; kc < 3; kc++) {
            uint32_t abuf = sbase + kc * A_CHB * 16;
            uint32_t bbuf = bbase + kc * B_CHB * 16;
#pragma unroll
            for (int ks = 0; ks < 4; ks++) {
                uint32_t a[2][4], b[2][4];
                int achk = 2 * ks + lhi;
#pragma unroll
                for (int mt = 0; mt < 2; mt++) {
                    uint32_t idx = (a_lrow + mt * 16) * 8 + (achk ^ a_sw);
                    ldsm_x4(abuf + idx * 16, a[mt]);
                }
                int bchk = 2 * ks + b_chlo;
#pragma unroll
                for (int nt16 = 0; nt16 < 2; nt16++) {
                    uint32_t idx = (b_lrow + nt16 * 16) * 8 + (bchk ^ b_sw);
                    ldsm_x4(bbuf + idx * 16, b[nt16]);
                }
#pragma unroll
                for (int mt = 0; mt < 2; mt++) {
#pragma unroll
                    for (int nt16 = 0; nt16 < 2; nt16++) {
                        mma_bf16(acc[mt][nt16 * 2 + 0], a[mt], &b[nt16][0]);
                        mma_bf16(acc[mt][nt16 * 2 + 1], a[mt], &b[nt16][2]);
                    }
                }
            }
        }
        __syncthreads();

        if (nt + 2 < NT) {
            const __nv_bfloat16* Bb = BT + (size_t)(nt + 2) * 64 * CC;
            uint32_t dst0 = sbase + ABYTES + (nt & 1) * BBYTES;
#pragma unroll
            for (int kc = 0; kc < 3; kc++) {
                uint32_t dst = dst0 + kc * B_CHB * 16;
                int k0 = kc << 6;
#pragma unroll
                for (int i = 0; i < 2; i++) {
                    int ch = b_ch0 + i;
                    cpasync16(dst + (b_row * 8 + (ch ^ (b_row & 7))) * 16,
                              Bb + (size_t)b_row * CC + k0 + ch * 8);
                }
            }
        }
        cp_commit();

        int n0 = nt * 64;
#pragma unroll
        for (int mt = 0; mt < 2; mt++) {
            int g0 = m0 + wm * 32 + mt * 16 + (lane >> 2);
            int g1 = g0 + 8;
            size_t ob0 = (size_t)g0 * NOUT;
            size_t ob1 = (size_t)g1 * NOUT;
#pragma unroll
            for (int ne = 0; ne < 4; ne++) {
                int col = n0 + wn * 32 + ne * 8 + 2 * (lane & 3);
                float b0 = bias[col], b1 = bias[col + 1];
                float2 v0 = make_float2(acc[mt][ne][0] + b0, acc[mt][ne][1] + b1);
                float2 v1 = make_float2(acc[mt][ne][2] + b0, acc[mt][ne][3] + b1);
                v0.x = gelu_exact(v0.x); v0.y = gelu_exact(v0.y);
                v1.x = gelu_exact(v1.x); v1.y = gelu_exact(v1.y);
                *(__nv_bfloat162*)(out + ob0 + col) = __float22bfloat162_rn(v0);
                *(__nv_bfloat162*)(out + ob1 + col) = __float22bfloat162_rn(v1);
            }
        }
    }
}

// ---------------------------------------------------------------------------
// FC2 GEMM (K=768): 3-stage circular pipeline. +bias +res -> fp32.
// ---------------------------------------------------------------------------
#define FC2_SMEM (3 * CH_PER_BUF * 16)

__global__ void __launch_bounds__(256) gemm_fc2(
    const __nv_bfloat16* __restrict__ A, const __nv_bfloat16* __restrict__ BT,
    const float* __restrict__ bias, const float* __restrict__ res,
    float* __restrict__ out) {
    extern __shared__ __align__(16) uint4 fsmq[];
    uint32_t sbase = smem_u32(fsmq);
    const int K = HIDDEN;
    const int NCH = K >> 6;
    int tid = threadIdx.x;
    int wid = tid >> 5, lane = tid & 31;
    int wm = wid & 3, wn = wid >> 2;
    int m0 = blockIdx.y * 128, n0 = blockIdx.x * 64;
    const __nv_bfloat16* Ab = A + (size_t)m0 * K;
    const __nv_bfloat16* Bb = BT + (size_t)n0 * K;

    float acc[2][4][4];
#pragma unroll
    for (int i = 0; i < 2; i++)
#pragma unroll
        for (int j = 0; j < 4; j++)
#pragma unroll
            for (int k = 0; k < 4; k++) acc[i][j][k] = 0.f;

    int a_row = tid >> 1;
    int a_ch0 = (tid & 1) * 4;
    int b_row = tid >> 2;
    int b_ch0 = (tid & 3) * 2;

    int l15 = lane & 15, lhi = lane >> 4;
    int a_lrow = wm * 32 + l15;
    int a_sw = l15 & 7;
    int b_lrow = 128 + wn * 32 + (lhi << 3) + (lane & 7);
    int b_sw = lane & 7;
    int b_chlo = (lane >> 3) & 1;

#pragma unroll
    for (int c = 0; c < 2; c++) {
        uint32_t dst = sbase + c * CH_PER_BUF * 16;
        int k0 = c << 6;
#pragma unroll
        for (int i = 0; i < 4; i++) {
            int ch = a_ch0 + i;
            cpasync16(dst + (a_row * 8 + (ch ^ (a_row & 7))) * 16,
                      Ab + (size_t)a_row * K + k0 + ch * 8);
        }
#pragma unroll
        for (int i = 0; i < 2; i++) {
            int ch = b_ch0 + i;
            cpasync16(dst + ((128 + b_row) * 8 + (ch ^ (b_row & 7))) * 16,
                      Bb + (size_t)b_row * K + k0 + ch * 8);
        }
        cp_commit();
    }

    int bufsel = 0;
    for (int c = 0; c < NCH; c++) {
        cp_wait1();
        __syncthreads();

        if (c + 2 < NCH) {
            int nb = bufsel + 2; if (nb >= 3) nb -= 3;
            uint32_t dst = sbase + nb * CH_PER_BUF * 16;
            int k0 = (c + 2) << 6;
#pragma unroll
            for (int i = 0; i < 4; i++) {
                int ch = a_ch0 + i;
                cpasync16(dst + (a_row * 8 + (ch ^ (a_row & 7))) * 16,
                          Ab + (size_t)a_row * K + k0 + ch * 8);
            }
#pragma unroll
            for (int i = 0; i < 2; i++) {
                int ch = b_ch0 + i;
                cpasync16(dst + ((128 + b_row) * 8 + (ch ^ (b_row & 7))) * 16,
                          Bb + (size_t)b_row * K + k0 + ch * 8);
            }
        }
        cp_commit();

        uint32_t buf = sbase + bufsel * CH_PER_BUF * 16;
#pragma unroll
        for (int ks = 0; ks < 4; ks++) {
            uint32_t a[2][4], b[2][4];
            int achk = 2 * ks + lhi;
#pragma unroll
            for (int mt = 0; mt < 2; mt++) {
                uint32_t idx = (a_lrow + mt * 16) * 8 + (achk ^ a_sw);
                ldsm_x4(buf + idx * 16, a[mt]);
            }
            int bchk = 2 * ks + b_chlo;
#pragma unroll
            for (int nt16 = 0; nt16 < 2; nt16++) {
                uint32_t idx = (b_lrow + nt16 * 16) * 8 + (bchk ^ b_sw);
                ldsm_x4(buf + idx * 16, b[nt16]);
            }
#pragma unroll
            for (int mt = 0; mt < 2; mt++) {
#pragma unroll
                for (int nt16 = 0; nt16 < 2; nt16++) {
                    mma_bf16(acc[mt][nt16 * 2 + 0], a[mt], &b[nt16][0]);
                    mma_bf16(acc[mt][nt16 * 2 + 1], a[mt], &b[nt16][2]);
                }
            }
        }
        bufsel++; if (bufsel == 3) bufsel = 0;
    }

#pragma unroll
    for (int mt = 0; mt < 2; mt++) {
        int g0 = m0 + wm * 32 + mt * 16 + (lane >> 2);
        int g1 = g0 + 8;
        size_t ob0 = (size_t)g0 * CC;
        size_t ob1 = (size_t)g1 * CC;
#pragma unroll
        for (int nt = 0; nt < 4; nt++) {
            int col = n0 + wn * 32 + nt * 8 + 2 * (lane & 3);
            float b0 = bias[col], b1 = bias[col + 1];
            float2 v0 = make_float2(acc[mt][nt][0] + b0, acc[mt][nt][1] + b1);
            float2 v1 = make_float2(acc[mt][nt][2] + b0, acc[mt][nt][3] + b1);
            float2 r0 = *(const float2*)(res + ob0 + col);
            float2 r1 = *(const float2*)(res + ob1 + col);
            v0.x += r0.x; v0.y += r0.y;
            v1.x += r1.x; v1.y += r1.y;
            *(float2*)(out + ob0 + col) = v0;
            *(float2*)(out + ob1 + col) = v1;
        }
    }
}

// ---------------------------------------------------------------------------
// Proj GEMM + scatter + residual + LN2 (fused)
// ---------------------------------------------------------------------------
#define PCH_PER_BUF (320 * 8)
#define PROJ_SMEM (2 * PCH_PER_BUF * 16)

__global__ void __launch_bounds__(256) gemm_proj_ln(
    const __nv_bfloat16* __restrict__ A, const __nv_bfloat16* __restrict__ BT,
    const float* __restrict__ bias, const float* __restrict__ x,
    float* __restrict__ y, __nv_bfloat16* __restrict__ ln2out,
    const float* __restrict__ n2g, const float* __restrict__ n2b) {
    extern __shared__ __align__(16) uint4 psm[];
    uint32_t sbase = smem_u32(psm);
    int tid = threadIdx.x;
    int wid = tid >> 5, lane = tid & 31;
    int m0 = blockIdx.x * 128;
    const __nv_bfloat16* Ab = A + (size_t)m0 * CC;

    float acc[24][4];
#pragma unroll
    for (int j = 0; j < 24; j++)
#pragma unroll
        for (int k = 0; k < 4; k++) acc[j][k] = 0.f;

    int a_row = tid >> 1;
    int a_ch0 = (tid & 1) * 4;
    int b_row = tid >> 2;
    int b_ch0 = (tid & 3) * 2;

    int l15 = lane & 15, lhi = lane >> 4;
    int a_lrow = wid * 16 + l15;
    int a_sw = l15 & 7;
    int b_lbase = 128 + (lhi << 3) + (lane & 7);
    int b_sw = lane & 7;
    int b_chlo = (lane >> 3) & 1;

    {
        uint32_t dst = sbase;
#pragma unroll
        for (int i = 0; i < 4; i++) {
            int ch = a_ch0 + i;
            cpasync16(dst + (a_row * 8 + (ch ^ (a_row & 7))) * 16,
                      Ab + (size_t)a_row * CC + ch * 8);
        }
#pragma unroll
        for (int r3 = 0; r3 < 3; r3++) {
            int row = r3 * 64 + b_row;
#pragma unroll
            for (int i = 0; i < 2; i++) {
                int ch = b_ch0 + i;
                cpasync16(dst + ((128 + row) * 8 + (ch ^ (row & 7))) * 16,
                          BT + (size_t)row * CC + ch * 8);
            }
        }
        cp_commit();
    }

    for (int c = 0; c < 3; c++) {
        if (c + 1 < 3) {
            int k0 = (c + 1) << 6;
            uint32_t dst = sbase + ((c + 1) & 1) * PCH_PER_BUF * 16;
#pragma unroll
            for (int i = 0; i < 4; i++) {
                int ch = a_ch0 + i;
                cpasync16(dst + (a_row * 8 + (ch ^ (a_row & 7))) * 16,
                          Ab + (size_t)a_row * CC + k0 + ch * 8);
            }
#pragma unroll
            for (int r3 = 0; r3 < 3; r3++) {
                int row = r3 * 64 + b_row;
#pragma unroll
                for (int i = 0; i < 2; i++) {
                    int ch = b_ch0 + i;
                    cpasync16(dst + ((128 + row) * 8 + (ch ^ (row & 7))) * 16,
                              BT + (size_t)row * CC + k0 + ch * 8);
                }
            }
        }
        cp_commit();
        cp_wait1();
        __syncthreads();

        uint32_t buf = sbase + (c & 1) * PCH_PER_BUF * 16;
#pragma unroll
        for (int ks = 0; ks < 4; ks++) {
            uint32_t a[4];
            int achk = 2 * ks + lhi;
            ldsm_x4(buf + (a_lrow * 8 + (achk ^ a_sw)) * 16, a);
            int bchk = 2 * ks + b_chlo;
#pragma unroll
            for (int nt16 = 0; nt16 < 12; nt16++) {
                uint32_t b[4];
                ldsm_x4(buf + ((b_lbase + nt16 * 16) * 8 + (bchk ^ b_sw)) * 16, b);
                mma_bf16(acc[nt16 * 2 + 0], a, &b[0]);
                mma_bf16(acc[nt16 * 2 + 1], a, &b[2]);
            }
        }
        __syncthreads();
    }

    int lq = lane & 3;
#pragma unroll
    for (int half = 0; half < 2; half++) {
        int g = m0 + wid * 16 + (lane >> 2) + half * 8;
        int bb = g >> 14, rem = g & 16383;
        int win = rem >> 6, rr = rem & 63;
        int wy = win >> 4, wx = win & 15, ry = rr >> 3, rx = rr & 7;
        int hh = (wy * WS + ry + SHIFT) & 127;
        int ww = (wx * WS + rx + SHIFT) & 127;
        size_t ob = ((size_t)bb * LL + hh * WW_ + ww) * CC;

        float vals[48];
        float s = 0.f, s2 = 0.f;
#pragma unroll
        for (int nt = 0; nt < 24; nt++) {
            int col = nt * 8 + 2 * lq;
            float v0 = acc[nt][half * 2 + 0] + bias[col];
            float v1 = acc[nt][half * 2 + 1] + bias[col + 1];
            float2 rv = *(const float2*)(x + ob + col);
            v0 += rv.x; v1 += rv.y;
            *(float2*)(y + ob + col) = make_float2(v0, v1);
            s += v0 + v1;
            s2 += v0 * v0 + v1 * v1;
            vals[nt * 2] = v0; vals[nt * 2 + 1] = v1;
        }
        s += __shfl_xor_sync(0xFFFFFFFFu, s, 1);
        s2 += __shfl_xor_sync(0xFFFFFFFFu, s2, 1);
        s += __shfl_xor_sync(0xFFFFFFFFu, s, 2);
        s2 += __shfl_xor_sync(0xFFFFFFFFu, s2, 2);
        float mu = s * (1.0f / 192.0f);
        float rs = rsqrtf(s2 * (1.0f / 192.0f) - mu * mu + 1e-5f);
#pragma unroll
        for (int nt = 0; nt < 24; nt++) {
            int col = nt * 8 + 2 * lq;
            float2 gg = *(const float2*)(n2g + col);
            float2 bb2 = *(const float2*)(n2b + col);
            float2 o;
            o.x = (vals[nt * 2] - mu) * rs * gg.x + bb2.x;
            o.y = (vals[nt * 2 + 1] - mu) * rs * gg.y + bb2.y;
            *(__nv_bfloat162*)(ln2out + ob + col) = __float22bfloat162_rn(o);
        }
    }
}

// ---------------------------------------------------------------------------
// Tensor-core windowed attention (round-13 version)
// ---------------------------------------------------------------------------
#define KSTR 200
#define VSTR 72
#define ATTN_SMEM ((2 * NWIN * KSTR + CC * VSTR) * 2)

__global__ void __launch_bounds__(384) attn_kernel(
    const __nv_bfloat16* __restrict__ qkv, __nv_bfloat16* __restrict__ outp) {
    extern __shared__ __nv_bfloat16 smh[];
    __nv_bfloat16* q_s = smh;
    __nv_bfloat16* k_s = smh + NWIN * KSTR;
    __nv_bfloat16* vt_s = smh + 2 * NWIN * KSTR;

    int w = blockIdx.x;
    int tid = threadIdx.x;
    int lane = tid & 31, wid = tid >> 5;
    const __nv_bfloat16* base = qkv + (size_t)w * NWIN * 576;

    for (int idx = tid; idx < NWIN * 24; idx += 384) {
        int j = idx / 24, c = idx % 24;
        const __nv_bfloat16* rowp = base + (size_t)j * 576 + c * 8;
        uint4 uq = *(const uint4*)(rowp);
        *(uint4*)(q_s + j * KSTR + c * 8) = uq;
        uint4 uk = *(const uint4*)(rowp + 192);
        *(uint4*)(k_s + j * KSTR + c * 8) = uk;
        uint4 uv = *(const uint4*)(rowp + 384);
        const unsigned short* e = (const unsigned short*)&uv;
#pragma unroll
        for (int i = 0; i < 8; i++) {
            int k = (i + lane) & 7;
            *((unsigned short*)vt_s + (c * 8 + k) * VSTR + j) = e[k];
        }
    }
    __syncthreads();

    int h = wid >> 1;
    int mbase = (wid & 1) * 32;
    int winloc = w & 255;
    int wy = winloc >> 4, wx = winloc & 15;
    int type = ((wy == 15) ? 2 : 0) | ((wx == 15) ? 1 : 0);
    const float* btab = g_bias + ((size_t)(type * HEADS + h) * NWIN) * NWIN;

    int rq = lane >> 2, cq = 2 * (lane & 3);
    int l15 = lane & 15, lhi = lane >> 4;
    int brow = (lhi << 3) + (lane & 7);
    int bchlo = (lane >> 3) & 1;

    uint32_t qsm = smem_u32(q_s);
    uint32_t a[2][2][4];
#pragma unroll
    for (int mt = 0; mt < 2; mt++)
#pragma unroll
        for (int ks = 0; ks < 2; ks++) {
            uint32_t addr = qsm +
                ((mbase + mt * 16 + l15) * KSTR + h * HD + ks * 16 + lhi * 8) * 2;
            ldsm_x4(addr, a[mt][ks]);
        }

    float p[2][8][4];
#pragma unroll
    for (int i = 0; i < 2; i++)
#pragma unroll
        for (int j = 0; j < 8; j++)
#pragma unroll
            for (int k = 0; k < 4; k++) p[i][j][k] = 0.f;

    uint32_t ksm = smem_u32(k_s);
#pragma unroll
    for (int kg = 0; kg < 4; kg++) {
#pragma unroll
        for (int ks = 0; ks < 2; ks++) {
            uint32_t b[4];
            uint32_t addr = ksm + ((kg * 16 + brow) * KSTR + (h * 4 + ks * 2 + bchlo) * 8) * 2;
            ldsm_x4(addr, b);
#pragma unroll
            for (int mt = 0; mt < 2; mt++) {
                mma_bf16(p[mt][kg * 2 + 0], a[mt][ks], &b[0]);
                mma_bf16(p[mt][kg * 2 + 1], a[mt][ks], &b[2]);
            }
        }
    }

    float sums[2][2];
#pragma unroll
    for (int mt = 0; mt < 2; mt++) {
#pragma unroll
        for (int rl = 0; rl < 2; rl++) {
            int r = mbase + mt * 16 + rq + rl * 8;
            const float* br_ = btab + r * NWIN;
            float m = -1e30f;
#pragma unroll
            for (int nt = 0; nt < 8; nt++) {
                float2 bv = *(const float2*)(br_ + nt * 8 + cq);
                p[mt][nt][rl * 2 + 0] += bv.x;
                p[mt][nt][rl * 2 + 1] += bv.y;
                m = fmaxf(m, fmaxf(p[mt][nt][rl * 2], p[mt][nt][rl * 2 + 1]));
            }
            m = fmaxf(m, __shfl_xor_sync(0xFFFFFFFFu, m, 1));
            m = fmaxf(m, __shfl_xor_sync(0xFFFFFFFFu, m, 2));
            float s = 0.f;
#pragma unroll
            for (int nt = 0; nt < 8; nt++) {
                float e0 = __expf(p[mt][nt][rl * 2] - m);
                float e1 = __expf(p[mt][nt][rl * 2 + 1] - m);
                p[mt][nt][rl * 2] = e0; p[mt][nt][rl * 2 + 1] = e1;
                s += e0 + e1;
            }
            s += __shfl_xor_sync(0xFFFFFFFFu, s, 1);
            s += __shfl_xor_sync(0xFFFFFFFFu, s, 2);
            sums[mt][rl] = s;
        }
    }

    uint32_t pa[2][4][4];
#pragma unroll
    for (int mt = 0; mt < 2; mt++)
#pragma unroll
        for (int s4 = 0; s4 < 4; s4++) {
            pa[mt][s4][0] = packbf2(p[mt][2 * s4][0], p[mt][2 * s4][1]);
            pa[mt][s4][1] = packbf2(p[mt][2 * s4][2], p[mt][2 * s4][3]);
            pa[mt][s4][2] = packbf2(p[mt][2 * s4 + 1][0], p[mt][2 * s4 + 1][1]);
            pa[mt][s4][3] = packbf2(p[mt][2 * s4 + 1][2], p[mt][2 * s4 + 1][3]);
        }

    float o[2][4][4];
#pragma unroll
    for (int i = 0; i < 2; i++)
#pragma unroll
        for (int j = 0; j < 4; j++)
#pragma unroll
            for (int k = 0; k < 4; k++) o[i][j][k] = 0.f;

    uint32_t vsm = smem_u32(vt_s);
#pragma unroll
    for (int s4 = 0; s4 < 4; s4++) {
#pragma unroll
        for (int n16 = 0; n16 < 2; n16++) {
            uint32_t b[4];
            uint32_t addr = vsm + ((h * HD + n16 * 16 + brow) * VSTR + (s4 * 2 + bchlo) * 8) * 2;
            ldsm_x4(addr, b);
#pragma unroll
            for (int mt = 0; mt < 2; mt++) {
                mma_bf16(o[mt][n16 * 2 + 0], pa[mt][s4], &b[0]);
                mma_bf16(o[mt][n16 * 2 + 1], pa[mt][s4], &b[2]);
            }
        }
    }

#pragma unroll
    for (int mt = 0; mt < 2; mt++) {
        float i0 = 1.0f / sums[mt][0];
        float i1 = 1.0f / sums[mt][1];
        int r0 = mbase + mt * 16 + rq;
        __nv_bfloat16* op0 = outp + (size_t)(w * NWIN + r0) * CC + h * HD;
        __nv_bfloat16* op1 = op0 + 8 * CC;
#pragma unroll
        for (int nt = 0; nt < 4; nt++) {
            *(__nv_bfloat162*)(op0 + nt * 8 + cq) =
                __float22bfloat162_rn(make_float2(o[mt][nt][0] * i0, o[mt][nt][1] * i0));
            *(__nv_bfloat162*)(op1 + nt * 8 + cq) =
                __float22bfloat162_rn(make_float2(o[mt][nt][2] * i1, o[mt][nt][3] * i1));
        }
    }
}

// ---------------------------------------------------------------------------
// Launch
// ---------------------------------------------------------------------------
extern "C" void kernel_launch(void* const* d_in, const int* in_sizes, int n_in,
                              void* d_out, int out_size) {
    const float* x      = (const float*)d_in[0];
    const float* n1_g   = (const float*)d_in[4];
    const float* n1_b   = (const float*)d_in[5];
    const float* qkv_w  = (const float*)d_in[6];
    const float* qkv_b  = (const float*)d_in[7];
    const float* proj_w = (const float*)d_in[8];
    const float* proj_b = (const float*)d_in[9];
    const float* pp_w   = (const float*)d_in[10];
    const float* pp_b   = (const float*)d_in[11];
    const float* p1_g   = (const float*)d_in[12];
    const float* p1_b   = (const float*)d_in[13];
    const float* p1_w   = (const float*)d_in[14];
    const float* p1_bi  = (const float*)d_in[15];
    const float* p2_g   = (const float*)d_in[16];
    const float* p2_b   = (const float*)d_in[17];
    const float* p2_w   = (const float*)d_in[18];
    const float* p2_bi  = (const float*)d_in[19];
    const float* p3_g   = (const float*)d_in[20];
    const float* p3_b   = (const float*)d_in[21];
    const float* p3_w   = (const float*)d_in[22];
    const float* p3_bi  = (const float*)d_in[23];
    const float* n2_g   = (const float*)d_in[24];
    const float* n2_b   = (const float*)d_in[25];
    const float* fc1_w  = (const float*)d_in[26];
    const float* fc1_b  = (const float*)d_in[27];
    const float* fc2_w  = (const float*)d_in[28];
    const float* fc2_b  = (const float*)d_in[29];
    float* out = (float*)d_out;

    __nv_bfloat16 *qkv, *attn, *ln2, *hid;
    __nv_bfloat16 *wt_qkv, *wt_proj, *wt_fc1, *wt_fc2;
    cudaGetSymbolAddress((void**)&qkv,  gb_qkv);
    cudaGetSymbolAddress((void**)&attn, gb_attn);
    cudaGetSymbolAddress((void**)&ln2,  gb_ln2);
    cudaGetSymbolAddress((void**)&hid,  gb_hid);
    cudaGetSymbolAddress((void**)&wt_qkv,  gb_wt_qkv);
    cudaGetSymbolAddress((void**)&wt_proj, gb_wt_proj);
    cudaGetSymbolAddress((void**)&wt_fc1,  gb_wt_fc1);
    cudaGetSymbolAddress((void**)&wt_fc2,  gb_wt_fc2);

    static bool attr_set = false;
    if (!attr_set) {
        cudaFuncSetAttribute(attn_kernel, cudaFuncAttributeMaxDynamicSharedMemorySize,
                             ATTN_SMEM);
        cudaFuncSetAttribute(gemm_proj_ln, cudaFuncAttributeMaxDynamicSharedMemorySize,
                             PROJ_SMEM);
        cudaFuncSetAttribute(gemm_ln1_qkv, cudaFuncAttributeMaxDynamicSharedMemorySize,
                             KM_SMEM);
        cudaFuncSetAttribute(gemm_k192_multi, cudaFuncAttributeMaxDynamicSharedMemorySize,
                             KM_SMEM);
        cudaFuncSetAttribute(gemm_fc2, cudaFuncAttributeMaxDynamicSharedMemorySize,
                             FC2_SMEM);
        attr_set = true;
    }

    // 0. weight transposes
    transpose_all<<<(TW_TOTAL + 255) / 256, 256>>>(qkv_w, proj_w, fc1_w, fc2_w);

    // 1. bias table with inline position-MLP
    bias_build<<<(4 * HEADS * NWIN * NWIN + 255) / 256, 256>>>(
        pp_w, pp_b, p1_g, p1_b, p1_w, p1_bi,
        p2_g, p2_b, p2_w, p2_bi, p3_g, p3_b, p3_w, p3_bi);

    // 2. fused LN1 + QKV GEMM (multi-N, A resident) -> bf16, Q pre-scaled
    gemm_ln1_qkv<<<MROWS / 128, 256, KM_SMEM>>>(x, wt_qkv, n1_g, n1_b, qkv_b, qkv);

    // 3. tensor-core attention -> bf16
    attn_kernel<<<NWINDOWS, 384, ATTN_SMEM>>>(qkv, attn);

    // 4. proj + scatter + residual + LN2 (fused)
    gemm_proj_ln<<<MROWS / 128, 256, PROJ_SMEM>>>(attn, wt_proj, proj_b, x, out, ln2, n2_g, n2_b);

    // 5. FC1 + GELU (multi-N, A resident) -> bf16
    gemm_k192_multi<<<MROWS / 128, 256, KM_SMEM>>>(ln2, wt_fc1, fc1_b, hid, HIDDEN);

    // 6. FC2 + residual -> fp32 out (3-stage pipeline, K=768)
    gemm_fc2<<<dim3(CC / 64, MROWS / 128), 256, FC2_SMEM>>>(hid, wt_fc2, fc2_b, out, out);
}

// round 16
// speedup vs baseline: 1.0265x; 1.0265x over previous
#include <cuda_runtime.h>
#include <cuda_bf16.h>
#include <math.h>
#include <stdint.h>

// ---------------------------------------------------------------------------
// Problem constants
// ---------------------------------------------------------------------------
#define BATCH   8
#define HH      128
#define WW_     128
#define LL      (HH*WW_)
#define CC      192
#define HEADS   6
#define HD      32
#define WS      8
#define NWIN    64
#define SHIFT   4
#define HIDDEN  768
#define MROWS   (BATCH*LL)                 // 131072
#define NWINDOWS (BATCH*(HH/WS)*(WW_/WS))  // 2048
#define POS_DIM 12
#define POS_TAB 225
#define QSCALE  0.17677669529663687f

// ---------------------------------------------------------------------------
// Device scratch
// ---------------------------------------------------------------------------
__device__ __nv_bfloat16 gb_xw[(size_t)MROWS * CC];
__device__ __nv_bfloat16 gb_qkv[(size_t)MROWS * 3 * CC];
__device__ __nv_bfloat16 gb_attn[(size_t)MROWS * CC];
__device__ __nv_bfloat16 gb_ln2[(size_t)MROWS * CC];
__device__ __nv_bfloat16 gb_hid[(size_t)MROWS * HIDDEN];
__device__ float g_bias[4 * HEADS * NWIN * NWIN];
__device__ __nv_bfloat16 gb_wt_qkv[3 * CC * CC];
__device__ __nv_bfloat16 gb_wt_proj[CC * CC];
__device__ __nv_bfloat16 gb_wt_fc1[HIDDEN * CC];
__device__ __nv_bfloat16 gb_wt_fc2[CC * HIDDEN];

// ---------------------------------------------------------------------------
// Helpers
// ---------------------------------------------------------------------------
__device__ __forceinline__ uint32_t smem_u32(const void* p) {
    uint32_t a;
    asm("{ .reg .u64 t; cvta.to.shared.u64 t, %1; cvt.u32.u64 %0, t; }" : "=r"(a) : "l"(p));
    return a;
}
__device__ __forceinline__ void cpasync16(uint32_t s, const void* g) {
    asm volatile("cp.async.cg.shared.global [%0], [%1], 16;" :: "r"(s), "l"(g));
}
__device__ __forceinline__ void cp_commit() {
    asm volatile("cp.async.commit_group;" ::: "memory");
}
__device__ __forceinline__ void cp_wait1() {
    asm volatile("cp.async.wait_group 1;" ::: "memory");
}
__device__ __forceinline__ void ldsm_x4(uint32_t addr, uint32_t* r) {
    asm volatile("ldmatrix.sync.aligned.m8n8.x4.shared.b16 {%0,%1,%2,%3}, [%4];"
                 : "=r"(r[0]), "=r"(r[1]), "=r"(r[2]), "=r"(r[3]) : "r"(addr));
}
__device__ __forceinline__ void mma_bf16(float* d, const uint32_t* a, const uint32_t* b) {
    asm volatile(
        "mma.sync.aligned.m16n8k16.row.col.f32.bf16.bf16.f32 "
        "{%0,%1,%2,%3}, {%4,%5,%6,%7}, {%8,%9}, {%0,%1,%2,%3};"
        : "+f"(d[0]), "+f"(d[1]), "+f"(d[2]), "+f"(d[3])
        : "r"(a[0]), "r"(a[1]), "r"(a[2]), "r"(a[3]), "r"(b[0]), "r"(b[1]));
}
__device__ __forceinline__ uint32_t packbf2(float x, float y) {
    __nv_bfloat162 t = __float22bfloat162_rn(make_float2(x, y));
    return *(uint32_t*)&t;
}
__device__ __forceinline__ float gelu_exact(float x) {
    return 0.5f * x * (1.0f + erff(x * 0.7071067811865476f));
}

// ---------------------------------------------------------------------------
// Combined weight transpose
// ---------------------------------------------------------------------------
#define TW_QKV (3*CC*CC)
#define TW_PROJ (CC*CC)
#define TW_FC1 (CC*HIDDEN)
#define TW_FC2 (HIDDEN*CC)
#define TW_TOTAL (TW_QKV + TW_PROJ + TW_FC1 + TW_FC2)

__global__ void transpose_all(const float* __restrict__ qkv_w, const float* __restrict__ proj_w,
                              const float* __restrict__ fc1_w, const float* __restrict__ fc2_w) {
    int i = blockIdx.x * 256 + threadIdx.x;
    if (i >= TW_TOTAL) return;
    const float* w; __nv_bfloat16* wt; int K, N, off;
    if (i < TW_QKV) { w = qkv_w; wt = gb_wt_qkv; K = CC; N = 3 * CC; off = i; }
    else if (i < TW_QKV + TW_PROJ) { w = proj_w; wt = gb_wt_proj; K = CC; N = CC; off = i - TW_QKV; }
    else if (i < TW_QKV + TW_PROJ + TW_FC1) { w = fc1_w; wt = gb_wt_fc1; K = CC; N = HIDDEN; off = i - TW_QKV - TW_PROJ; }
    else { w = fc2_w; wt = gb_wt_fc2; K = HIDDEN; N = CC; off = i - TW_QKV - TW_PROJ - TW_FC1; }
    int k = off / N, n = off % N;
    wt[(size_t)n * K + k] = __float2bfloat16(w[off]);
}

// ---------------------------------------------------------------------------
// Bias table with inline position-MLP
// ---------------------------------------------------------------------------
__device__ __forceinline__ void ln_relu12(const float* p, float* q,
                                          const float* g, const float* b) {
    float s = 0.f, s2 = 0.f;
#pragma unroll
    for (int i = 0; i < POS_DIM; i++) { s += p[i]; s2 += p[i] * p[i]; }
    float mu = s / 12.0f;
    float var = s2 / 12.0f - mu * mu;
    float rs = rsqrtf(var + 1e-5f);
#pragma unroll
    for (int i = 0; i < POS_DIM; i++) q[i] = fmaxf((p[i] - mu) * rs * g[i] + b[i], 0.0f);
}

__global__ void bias_build(
    const float* __restrict__ pp_w, const float* __restrict__ pp_b,
    const float* __restrict__ p1_g, const float* __restrict__ p1_b,
    const float* __restrict__ p1_w, const float* __restrict__ p1_bias,
    const float* __restrict__ p2_g, const float* __restrict__ p2_b,
    const float* __restrict__ p2_w, const float* __restrict__ p2_bias,
    const float* __restrict__ p3_g, const float* __restrict__ p3_b,
    const float* __restrict__ p3_w, const float* __restrict__ p3_bias) {
    int idx = blockIdx.x * 256 + threadIdx.x;
    if (idx >= 4 * HEADS * NWIN * NWIN) return;
    int j = idx & 63;
    int r = (idx >> 6) & 63;
    int h = (idx >> 12) % HEADS;
    int t = idx / (HEADS * NWIN * NWIN);
    int ry = r >> 3, rx = r & 7, jy = j >> 3, jx = j & 7;

    float bh = (float)(ry - jy), bw = (float)(rx - jx);
    float p[POS_DIM], q[POS_DIM];
#pragma unroll
    for (int k = 0; k < POS_DIM; k++) p[k] = bh * pp_w[k] + bw * pp_w[POS_DIM + k] + pp_b[k];
    ln_relu12(p, q, p1_g, p1_b);
#pragma unroll
    for (int k = 0; k < POS_DIM; k++) {
        float s = p1_bias[k];
#pragma unroll
        for (int i = 0; i < POS_DIM; i++) s += q[i] * p1_w[i * POS_DIM + k];
        p[k] = s;
    }
    ln_relu12(p, q, p2_g, p2_b);
#pragma unroll
    for (int k = 0; k < POS_DIM; k++) {
        float s = p2_bias[k];
#pragma unroll
        for (int i = 0; i < POS_DIM; i++) s += q[i] * p2_w[i * POS_DIM + k];
        p[k] = s;
    }
    ln_relu12(p, q, p3_g, p3_b);
    float bias = p3_bias[h];
#pragma unroll
    for (int i = 0; i < POS_DIM; i++) bias += q[i] * p3_w[i * HEADS + h];

    int lhr = (t & 2) ? (ry < (WS - SHIFT) ? 1 : 2) : 0;
    int lhj = (t & 2) ? (jy < (WS - SHIFT) ? 1 : 2) : 0;
    int lwr = (t & 1) ? (rx < (WS - SHIFT) ? 1 : 2) : 0;
    int lwj = (t & 1) ? (jx < (WS - SHIFT) ? 1 : 2) : 0;
    if (lhr != lhj || lwr != lwj) bias -= 100.0f;
    g_bias[idx] = bias;
}

// ---------------------------------------------------------------------------
// LayerNorm1: warp per row, fp32 in -> bf16 out, shift+window gather
// ---------------------------------------------------------------------------
__global__ void __launch_bounds__(256) ln1_kernel(
    const float* __restrict__ in, __nv_bfloat16* __restrict__ out,
    const float* __restrict__ gamma, const float* __restrict__ beta) {
    int warp = threadIdx.x >> 5, lane = threadIdx.x & 31;
    int row = blockIdx.x * 8 + warp;
    int bb = row >> 14, rem = row & 16383;
    int win = rem >> 6, r = rem & 63;
    int wy = win >> 4, wx = win & 15, ry = r >> 3, rx = r & 7;
    int hh = (wy * WS + ry + SHIFT) & 127;
    int ww = (wx * WS + rx + SHIFT) & 127;
    size_t src = (size_t)bb * LL + hh * WW_ + ww;

    const float* p = in + src * CC;
    float v[6], s = 0.f, s2 = 0.f;
#pragma unroll
    for (int k = 0; k < 6; k++) { v[k] = p[lane + 32 * k]; s += v[k]; s2 += v[k] * v[k]; }
#pragma unroll
    for (int o = 16; o > 0; o >>= 1) {
        s += __shfl_xor_sync(0xFFFFFFFFu, s, o);
        s2 += __shfl_xor_sync(0xFFFFFFFFu, s2, o);
    }
    float mu = s * (1.0f / 192.0f);
    float rs = rsqrtf(s2 * (1.0f / 192.0f) - mu * mu + 1e-5f);
    __nv_bfloat16* q = out + (size_t)row * CC;
#pragma unroll
    for (int k = 0; k < 6; k++) {
        int c = lane + 32 * k;
        q[c] = __float2bfloat16((v[k] - mu) * rs * gamma[c] + beta[c]);
    }
}

#define CH_PER_BUF (192 * 8)
#define A_CHB  (128 * 8)
#define B_CHB  (64 * 8)
#define ABYTES (3 * A_CHB * 16)
#define BBYTES (3 * B_CHB * 16)
#define KM_SMEM (ABYTES + 2 * BBYTES)

// ---------------------------------------------------------------------------
// K=192 multi-N GEMM (round-14): A resident, B double-buffered.
// EPI 0: +bias, Q-scale cols<192 -> bf16   1: gelu(+bias) -> bf16
// ---------------------------------------------------------------------------
template <int EPI>
__global__ void __launch_bounds__(256) gemm_k192_multi(
    const __nv_bfloat16* __restrict__ A, const __nv_bfloat16* __restrict__ BT,
    const float* __restrict__ bias, __nv_bfloat16* __restrict__ out, int NOUT) {
    extern __shared__ __align__(16) uint4 kmsq[];
    uint32_t sbase = smem_u32(kmsq);
    int tid = threadIdx.x;
    int wid = tid >> 5, lane = tid & 31;
    int wm = wid & 3, wn = wid >> 2;
    int m0 = blockIdx.x * 128;
    const int NT = NOUT >> 6;
    const __nv_bfloat16* Ab = A + (size_t)m0 * CC;

    int a_row = tid >> 1;
    int a_ch0 = (tid & 1) * 4;
    int b_row = tid >> 2;
    int b_ch0 = (tid & 3) * 2;

    int l15 = lane & 15, lhi = lane >> 4;
    int a_lrow = wm * 32 + l15;
    int a_sw = l15 & 7;
    int b_lrow = wn * 32 + (lhi << 3) + (lane & 7);
    int b_sw = lane & 7;
    int b_chlo = (lane >> 3) & 1;

#pragma unroll
    for (int kc = 0; kc < 3; kc++) {
        uint32_t dst = sbase + kc * A_CHB * 16;
        int k0 = kc << 6;
#pragma unroll
        for (int i = 0; i < 4; i++) {
            int ch = a_ch0 + i;
            cpasync16(dst + (a_row * 8 + (ch ^ (a_row & 7))) * 16,
                      Ab + (size_t)a_row * CC + k0 + ch * 8);
        }
    }
    {
        const __nv_bfloat16* Bb = BT;
#pragma unroll
        for (int kc = 0; kc < 3; kc++) {
            uint32_t dst = sbase + ABYTES + kc * B_CHB * 16;
            int k0 = kc << 6;
#pragma unroll
            for (int i = 0; i < 2; i++) {
                int ch = b_ch0 + i;
                cpasync16(dst + (b_row * 8 + (ch ^ (b_row & 7))) * 16,
                          Bb + (size_t)b_row * CC + k0 + ch * 8);
            }
        }
        cp_commit();
    }
    if (NT > 1) {
        const __nv_bfloat16* Bb = BT + (size_t)64 * CC;
#pragma unroll
        for (int kc = 0; kc < 3; kc++) {
            uint32_t dst = sbase + ABYTES + BBYTES + kc * B_CHB * 16;
            int k0 = kc << 6;
#pragma unroll
            for (int i = 0; i < 2; i++) {
                int ch = b_ch0 + i;
                cpasync16(dst + (b_row * 8 + (ch ^ (b_row & 7))) * 16,
                          Bb + (size_t)b_row * CC + k0 + ch * 8);
            }
        }
    }
    cp_commit();

    for (int nt = 0; nt < NT; nt++) {
        cp_wait1();
        __syncthreads();

        float acc[2][4][4];
#pragma unroll
        for (int i = 0; i < 2; i++)
#pragma unroll
            for (int j = 0; j < 4; j++)
#pragma unroll
                for (int k = 0; k < 4; k++) acc[i][j][k] = 0.f;

        uint32_t bbase = sbase + ABYTES + (nt & 1) * BBYTES;
#pragma unroll
        for (int kc = 0; kc < 3; kc++) {
            uint32_t abuf = sbase + kc * A_CHB * 16;
            uint32_t bbuf = bbase + kc * B_CHB * 16;
#pragma unroll
            for (int ks = 0; ks < 4; ks++) {
                uint32_t a[2][4], b[2][4];
                int achk = 2 * ks + lhi;
#pragma unroll
                for (int mt = 0; mt < 2; mt++) {
                    uint32_t idx = (a_lrow + mt * 16) * 8 + (achk ^ a_sw);
                    ldsm_x4(abuf + idx * 16, a[mt]);
                }
                int bchk = 2 * ks + b_chlo;
#pragma unroll
                for (int nt16 = 0; nt16 < 2; nt16++) {
                    uint32_t idx = (b_lrow + nt16 * 16) * 8 + (bchk ^ b_sw);
                    ldsm_x4(bbuf + idx * 16, b[nt16]);
                }
#pragma unroll
                for (int mt = 0; mt < 2; mt++) {
#pragma unroll
                    for (int nt16 = 0; nt16 < 2; nt16++) {
                        mma_bf16(acc[mt][nt16 * 2 + 0], a[mt], &b[nt16][0]);
                        mma_bf16(acc[mt][nt16 * 2 + 1], a[mt], &b[nt16][2]);
                    }
                }
            }
        }
        __syncthreads();

        if (nt + 2 < NT) {
            const __nv_bfloat16* Bb = BT + (size_t)(nt + 2) * 64 * CC;
            uint32_t dst0 = sbase + ABYTES + (nt & 1) * BBYTES;
#pragma unroll
            for (int kc = 0; kc < 3; kc++) {
                uint32_t dst = dst0 + kc * B_CHB * 16;
                int k0 = kc << 6;
#pragma unroll
                for (int i = 0; i < 2; i++) {
                    int ch = b_ch0 + i;
                    cpasync16(dst + (b_row * 8 + (ch ^ (b_row & 7))) * 16,
                              Bb + (size_t)b_row * CC + k0 + ch * 8);
                }
            }
        }
        cp_commit();

        int n0 = nt * 64;
#pragma unroll
        for (int mt = 0; mt < 2; mt++) {
            int g0 = m0 + wm * 32 + mt * 16 + (lane >> 2);
            int g1 = g0 + 8;
            size_t ob0 = (size_t)g0 * NOUT;
            size_t ob1 = (size_t)g1 * NOUT;
#pragma unroll
            for (int ne = 0; ne < 4; ne++) {
                int col = n0 + wn * 32 + ne * 8 + 2 * (lane & 3);
                float b0 = bias[col], b1 = bias[col + 1];
                float2 v0 = make_float2(acc[mt][ne][0] + b0, acc[mt][ne][1] + b1);
                float2 v1 = make_float2(acc[mt][ne][2] + b0, acc[mt][ne][3] + b1);
                if (EPI == 0) {
                    float sc = (col < CC) ? QSCALE : 1.0f;
                    v0.x *= sc; v0.y *= sc; v1.x *= sc; v1.y *= sc;
                }
                if (EPI == 1) {
                    v0.x = gelu_exact(v0.x); v0.y = gelu_exact(v0.y);
                    v1.x = gelu_exact(v1.x); v1.y = gelu_exact(v1.y);
                }
                *(__nv_bfloat162*)(out + ob0 + col) = __float22bfloat162_rn(v0);
                *(__nv_bfloat162*)(out + ob1 + col) = __float22bfloat162_rn(v1);
            }
        }
    }
}

// ---------------------------------------------------------------------------
// FC2 GEMM (K=768): 3-stage circular pipeline. +bias +res -> fp32.
// ---------------------------------------------------------------------------
#define FC2_SMEM (3 * CH_PER_BUF * 16)

__global__ void __launch_bounds__(256) gemm_fc2(
    const __nv_bfloat16* __restrict__ A, const __nv_bfloat16* __restrict__ BT,
    const float* __restrict__ bias, const float* __restrict__ res,
    float* __restrict__ out) {
    extern __shared__ __align__(16) uint4 fsmq[];
    uint32_t sbase = smem_u32(fsmq);
    const int K = HIDDEN;
    const int NCH = K >> 6;
    int tid = threadIdx.x;
    int wid = tid >> 5, lane = tid & 31;
    int wm = wid & 3, wn = wid >> 2;
    int m0 = blockIdx.y * 128, n0 = blockIdx.x * 64;
    const __nv_bfloat16* Ab = A + (size_t)m0 * K;
    const __nv_bfloat16* Bb = BT + (size_t)n0 * K;

    float acc[2][4][4];
#pragma unroll
    for (int i = 0; i < 2; i++)
#pragma unroll
        for (int j = 0; j < 4; j++)
#pragma unroll
            for (int k = 0; k < 4; k++) acc[i][j][k] = 0.f;

    int a_row = tid >> 1;
    int a_ch0 = (tid & 1) * 4;
    int b_row = tid >> 2;
    int b_ch0 = (tid & 3) * 2;

    int l15 = lane & 15, lhi = lane >> 4;
    int a_lrow = wm * 32 + l15;
    int a_sw = l15 & 7;
    int b_lrow = 128 + wn * 32 + (lhi << 3) + (lane & 7);
    int b_sw = lane & 7;
    int b_chlo = (lane >> 3) & 1;

#pragma unroll
    for (int c = 0; c < 2; c++) {
        uint32_t dst = sbase + c * CH_PER_BUF * 16;
        int k0 = c << 6;
#pragma unroll
        for (int i = 0; i < 4; i++) {
            int ch = a_ch0 + i;
            cpasync16(dst + (a_row * 8 + (ch ^ (a_row & 7))) * 16,
                      Ab + (size_t)a_row * K + k0 + ch * 8);
        }
#pragma unroll
        for (int i = 0; i < 2; i++) {
            int ch = b_ch0 + i;
            cpasync16(dst + ((128 + b_row) * 8 + (ch ^ (b_row & 7))) * 16,
                      Bb + (size_t)b_row * K + k0 + ch * 8);
        }
        cp_commit();
    }

    int bufsel = 0;
    for (int c = 0; c < NCH; c++) {
        cp_wait1();
        __syncthreads();

        if (c + 2 < NCH) {
            int nb = bufsel + 2; if (nb >= 3) nb -= 3;
            uint32_t dst = sbase + nb * CH_PER_BUF * 16;
            int k0 = (c + 2) << 6;
#pragma unroll
            for (int i = 0; i < 4; i++) {
                int ch = a_ch0 + i;
                cpasync16(dst + (a_row * 8 + (ch ^ (a_row & 7))) * 16,
                          Ab + (size_t)a_row * K + k0 + ch * 8);
            }
#pragma unroll
            for (int i = 0; i < 2; i++) {
                int ch = b_ch0 + i;
                cpasync16(dst + ((128 + b_row) * 8 + (ch ^ (b_row & 7))) * 16,
                          Bb + (size_t)b_row * K + k0 + ch * 8);
            }
        }
        cp_commit();

        uint32_t buf = sbase + bufsel * CH_PER_BUF * 16;
#pragma unroll
        for (int ks = 0; ks < 4; ks++) {
            uint32_t a[2][4], b[2][4];
            int achk = 2 * ks + lhi;
#pragma unroll
            for (int mt = 0; mt < 2; mt++) {
                uint32_t idx = (a_lrow + mt * 16) * 8 + (achk ^ a_sw);
                ldsm_x4(buf + idx * 16, a[mt]);
            }
            int bchk = 2 * ks + b_chlo;
#pragma unroll
            for (int nt16 = 0; nt16 < 2; nt16++) {
                uint32_t idx = (b_lrow + nt16 * 16) * 8 + (bchk ^ b_sw);
                ldsm_x4(buf + idx * 16, b[nt16]);
            }
#pragma unroll
            for (int mt = 0; mt < 2; mt++) {
#pragma unroll
                for (int nt16 = 0; nt16 < 2; nt16++) {
                    mma_bf16(acc[mt][nt16 * 2 + 0], a[mt], &b[nt16][0]);
                    mma_bf16(acc[mt][nt16 * 2 + 1], a[mt], &b[nt16][2]);
                }
            }
        }
        bufsel++; if (bufsel == 3) bufsel = 0;
    }

#pragma unroll
    for (int mt = 0; mt < 2; mt++) {
        int g0 = m0 + wm * 32 + mt * 16 + (lane >> 2);
        int g1 = g0 + 8;
        size_t ob0 = (size_t)g0 * CC;
        size_t ob1 = (size_t)g1 * CC;
#pragma unroll
        for (int nt = 0; nt < 4; nt++) {
            int col = n0 + wn * 32 + nt * 8 + 2 * (lane & 3);
            float b0 = bias[col], b1 = bias[col + 1];
            float2 v0 = make_float2(acc[mt][nt][0] + b0, acc[mt][nt][1] + b1);
            float2 v1 = make_float2(acc[mt][nt][2] + b0, acc[mt][nt][3] + b1);
            float2 r0 = *(const float2*)(res + ob0 + col);
            float2 r1 = *(const float2*)(res + ob1 + col);
            v0.x += r0.x; v0.y += r0.y;
            v1.x += r1.x; v1.y += r1.y;
            *(float2*)(out + ob0 + col) = v0;
            *(float2*)(out + ob1 + col) = v1;
        }
    }
}

// ---------------------------------------------------------------------------
// Proj GEMM + scatter + residual + LN2 (fused)
// ---------------------------------------------------------------------------
#define PCH_PER_BUF (320 * 8)
#define PROJ_SMEM (2 * PCH_PER_BUF * 16)

__global__ void __launch_bounds__(256) gemm_proj_ln(
    const __nv_bfloat16* __restrict__ A, const __nv_bfloat16* __restrict__ BT,
    const float* __restrict__ bias, const float* __restrict__ x,
    float* __restrict__ y, __nv_bfloat16* __restrict__ ln2out,
    const float* __restrict__ n2g, const float* __restrict__ n2b) {
    extern __shared__ __align__(16) uint4 psm[];
    uint32_t sbase = smem_u32(psm);
    int tid = threadIdx.x;
    int wid = tid >> 5, lane = tid & 31;
    int m0 = blockIdx.x * 128;
    const __nv_bfloat16* Ab = A + (size_t)m0 * CC;

    float acc[24][4];
#pragma unroll
    for (int j = 0; j < 24; j++)
#pragma unroll
        for (int k = 0; k < 4; k++) acc[j][k] = 0.f;

    int a_row = tid >> 1;
    int a_ch0 = (tid & 1) * 4;
    int b_row = tid >> 2;
    int b_ch0 = (tid & 3) * 2;

    int l15 = lane & 15, lhi = lane >> 4;
    int a_lrow = wid * 16 + l15;
    int a_sw = l15 & 7;
    int b_lbase = 128 + (lhi << 3) + (lane & 7);
    int b_sw = lane & 7;
    int b_chlo = (lane >> 3) & 1;

    {
        uint32_t dst = sbase;
#pragma unroll
        for (int i = 0; i < 4; i++) {
            int ch = a_ch0 + i;
            cpasync16(dst + (a_row * 8 + (ch ^ (a_row & 7))) * 16,
                      Ab + (size_t)a_row * CC + ch * 8);
        }
#pragma unroll
        for (int r3 = 0; r3 < 3; r3++) {
            int row = r3 * 64 + b_row;
#pragma unroll
            for (int i = 0; i < 2; i++) {
                int ch = b_ch0 + i;
                cpasync16(dst + ((128 + row) * 8 + (ch ^ (row & 7))) * 16,
                          BT + (size_t)row * CC + ch * 8);
            }
        }
        cp_commit();
    }

    for (int c = 0; c < 3; c++) {
        if (c + 1 < 3) {
            int k0 = (c + 1) << 6;
            uint32_t dst = sbase + ((c + 1) & 1) * PCH_PER_BUF * 16;
#pragma unroll
            for (int i = 0; i < 4; i++) {
                int ch = a_ch0 + i;
                cpasync16(dst + (a_row * 8 + (ch ^ (a_row & 7))) * 16,
                          Ab + (size_t)a_row * CC + k0 + ch * 8);
            }
#pragma unroll
            for (int r3 = 0; r3 < 3; r3++) {
                int row = r3 * 64 + b_row;
#pragma unroll
                for (int i = 0; i < 2; i++) {
                    int ch = b_ch0 + i;
                    cpasync16(dst + ((128 + row) * 8 + (ch ^ (row & 7))) * 16,
                              BT + (size_t)row * CC + k0 + ch * 8);
                }
            }
        }
        cp_commit();
        cp_wait1();
        __syncthreads();

        uint32_t buf = sbase + (c & 1) * PCH_PER_BUF * 16;
#pragma unroll
        for (int ks = 0; ks < 4; ks++) {
            uint32_t a[4];
            int achk = 2 * ks + lhi;
            ldsm_x4(buf + (a_lrow * 8 + (achk ^ a_sw)) * 16, a);
            int bchk = 2 * ks + b_chlo;
#pragma unroll
            for (int nt16 = 0; nt16 < 12; nt16++) {
                uint32_t b[4];
                ldsm_x4(buf + ((b_lbase + nt16 * 16) * 8 + (bchk ^ b_sw)) * 16, b);
                mma_bf16(acc[nt16 * 2 + 0], a, &b[0]);
                mma_bf16(acc[nt16 * 2 + 1], a, &b[2]);
            }
        }
        __syncthreads();
    }

    int lq = lane & 3;
#pragma unroll
    for (int half = 0; half < 2; half++) {
        int g = m0 + wid * 16 + (lane >> 2) + half * 8;
        int bb = g >> 14, rem = g & 16383;
        int win = rem >> 6, rr = rem & 63;
        int wy = win >> 4, wx = win & 15, ry = rr >> 3, rx = rr & 7;
        int hh = (wy * WS + ry + SHIFT) & 127;
        int ww = (wx * WS + rx + SHIFT) & 127;
        size_t ob = ((size_t)bb * LL + hh * WW_ + ww) * CC;

        float vals[48];
        float s = 0.f, s2 = 0.f;
#pragma unroll
        for (int nt = 0; nt < 24; nt++) {
            int col = nt * 8 + 2 * lq;
            float v0 = acc[nt][half * 2 + 0] + bias[col];
            float v1 = acc[nt][half * 2 + 1] + bias[col + 1];
            float2 rv = *(const float2*)(x + ob + col);
            v0 += rv.x; v1 += rv.y;
            *(float2*)(y + ob + col) = make_float2(v0, v1);
            s += v0 + v1;
            s2 += v0 * v0 + v1 * v1;
            vals[nt * 2] = v0; vals[nt * 2 + 1] = v1;
        }
        s += __shfl_xor_sync(0xFFFFFFFFu, s, 1);
        s2 += __shfl_xor_sync(0xFFFFFFFFu, s2, 1);
        s += __shfl_xor_sync(0xFFFFFFFFu, s, 2);
        s2 += __shfl_xor_sync(0xFFFFFFFFu, s2, 2);
        float mu = s * (1.0f / 192.0f);
        float rs = rsqrtf(s2 * (1.0f / 192.0f) - mu * mu + 1e-5f);
#pragma unroll
        for (int nt = 0; nt < 24; nt++) {
            int col = nt * 8 + 2 * lq;
            float2 gg = *(const float2*)(n2g + col);
            float2 bb2 = *(const float2*)(n2b + col);
            float2 o;
            o.x = (vals[nt * 2] - mu) * rs * gg.x + bb2.x;
            o.y = (vals[nt * 2 + 1] - mu) * rs * gg.y + bb2.y;
            *(__nv_bfloat162*)(ln2out + ob + col) = __float22bfloat162_rn(o);
        }
    }
}

// ---------------------------------------------------------------------------
// Tensor-core windowed attention, 768 threads = 24 warps:
// warp = (head, 16-row quarter). Q staged in SMEM, A-frags via ldmatrix.
// ---------------------------------------------------------------------------
#define KSTR 200
#define VSTR 72
#define ATTN_SMEM ((2 * NWIN * KSTR + CC * VSTR) * 2)

__global__ void __launch_bounds__(768) attn_kernel(
    const __nv_bfloat16* __restrict__ qkv, __nv_bfloat16* __restrict__ outp) {
    extern __shared__ __nv_bfloat16 smh[];
    __nv_bfloat16* q_s = smh;                       // [64][KSTR]
    __nv_bfloat16* k_s = smh + NWIN * KSTR;         // [64][KSTR]
    __nv_bfloat16* vt_s = smh + 2 * NWIN * KSTR;    // [192][VSTR]

    int w = blockIdx.x;
    int tid = threadIdx.x;
    int lane = tid & 31, wid = tid >> 5;
    const __nv_bfloat16* base = qkv + (size_t)w * NWIN * 576;

    for (int idx = tid; idx < NWIN * 24; idx += 768) {
        int j = idx / 24, c = idx % 24;
        const __nv_bfloat16* rowp = base + (size_t)j * 576 + c * 8;
        uint4 uq = *(const uint4*)(rowp);
        *(uint4*)(q_s + j * KSTR + c * 8) = uq;
        uint4 uk = *(const uint4*)(rowp + 192);
        *(uint4*)(k_s + j * KSTR + c * 8) = uk;
        uint4 uv = *(const uint4*)(rowp + 384);
        const unsigned short* e = (const unsigned short*)&uv;
#pragma unroll
        for (int i = 0; i < 8; i++) {
            int k = (i + lane) & 7;
            *((unsigned short*)vt_s + (c * 8 + k) * VSTR + j) = e[k];
        }
    }
    __syncthreads();

    int h = wid >> 2;                 // 0..5
    int mbase = (wid & 3) * 16;       // 0,16,32,48
    int winloc = w & 255;
    int wy = winloc >> 4, wx = winloc & 15;
    int type = ((wy == 15) ? 2 : 0) | ((wx == 15) ? 1 : 0);
    const float* btab = g_bias + ((size_t)(type * HEADS + h) * NWIN) * NWIN;

    int rq = lane >> 2, cq = 2 * (lane & 3);
    int l15 = lane & 15, lhi = lane >> 4;
    int brow = (lhi << 3) + (lane & 7);
    int bchlo = (lane >> 3) & 1;

    // A fragments (Q) via ldmatrix from smem: 16 rows x 32 cols
    uint32_t qsm = smem_u32(q_s);
    uint32_t a[2][4];
#pragma unroll
    for (int ks = 0; ks < 2; ks++) {
        uint32_t addr = qsm +
            ((mbase + l15) * KSTR + h * HD + ks * 16 + lhi * 8) * 2;
        ldsm_x4(addr, a[ks]);
    }

    // S = Q @ K^T : 16x64
    float p[8][4];
#pragma unroll
    for (int j = 0; j < 8; j++)
#pragma unroll
        for (int k = 0; k < 4; k++) p[j][k] = 0.f;

    uint32_t ksm = smem_u32(k_s);
#pragma unroll
    for (int kg = 0; kg < 4; kg++) {
#pragma unroll
        for (int ks = 0; ks < 2; ks++) {
            uint32_t b[4];
            uint32_t addr = ksm + ((kg * 16 + brow) * KSTR + (h * 4 + ks * 2 + bchlo) * 8) * 2;
            ldsm_x4(addr, b);
            mma_bf16(p[kg * 2 + 0], a[ks], &b[0]);
            mma_bf16(p[kg * 2 + 1], a[ks], &b[2]);
        }
    }

    // bias + softmax (rows rq and rq+8)
    float sums[2];
#pragma unroll
    for (int rl = 0; rl < 2; rl++) {
        int r = mbase + rq + rl * 8;
        const float* br_ = btab + r * NWIN;
        float m = -1e30f;
#pragma unroll
        for (int nt = 0; nt < 8; nt++) {
            float2 bv = *(const float2*)(br_ + nt * 8 + cq);
            p[nt][rl * 2 + 0] += bv.x;
            p[nt][rl * 2 + 1] += bv.y;
            m = fmaxf(m, fmaxf(p[nt][rl * 2], p[nt][rl * 2 + 1]));
        }
        m = fmaxf(m, __shfl_xor_sync(0xFFFFFFFFu, m, 1));
        m = fmaxf(m, __shfl_xor_sync(0xFFFFFFFFu, m, 2));
        float s = 0.f;
#pragma unroll
        for (int nt = 0; nt < 8; nt++) {
            float e0 = __expf(p[nt][rl * 2] - m);
            float e1 = __expf(p[nt][rl * 2 + 1] - m);
            p[nt][rl * 2] = e0; p[nt][rl * 2 + 1] = e1;
            s += e0 + e1;
        }
        s += __shfl_xor_sync(0xFFFFFFFFu, s, 1);
        s += __shfl_xor_sync(0xFFFFFFFFu, s, 2);
        sums[rl] = s;
    }

    // pack P to bf16 A-fragments
    uint32_t pa[4][4];
#pragma unroll
    for (int s4 = 0; s4 < 4; s4++) {
        pa[s4][0] = packbf2(p[2 * s4][0], p[2 * s4][1]);
        pa[s4][1] = packbf2(p[2 * s4][2], p[2 * s4][3]);
        pa[s4][2] = packbf2(p[2 * s4 + 1][0], p[2 * s4 + 1][1]);
        pa[s4][3] = packbf2(p[2 * s4 + 1][2], p[2 * s4 + 1][3]);
    }

    // O = P @ V : 16x32
    float o[4][4];
#pragma unroll
    for (int j = 0; j < 4; j++)
#pragma unroll
        for (int k = 0; k < 4; k++) o[j][k] = 0.f;

    uint32_t vsm = smem_u32(vt_s);
#pragma unroll
    for (int s4 = 0; s4 < 4; s4++) {
#pragma unroll
        for (int n16 = 0; n16 < 2; n16++) {
            uint32_t b[4];
            uint32_t addr = vsm + ((h * HD + n16 * 16 + brow) * VSTR + (s4 * 2 + bchlo) * 8) * 2;
            ldsm_x4(addr, b);
            mma_bf16(o[n16 * 2 + 0], pa[s4], &b[0]);
            mma_bf16(o[n16 * 2 + 1], pa[s4], &b[2]);
        }
    }

    // normalize + store
    float i0 = 1.0f / sums[0];
    float i1 = 1.0f / sums[1];
    int r0 = mbase + rq;
    __nv_bfloat16* op0 = outp + (size_t)(w * NWIN + r0) * CC + h * HD;
    __nv_bfloat16* op1 = op0 + 8 * CC;
#pragma unroll
    for (int nt = 0; nt < 4; nt++) {
        *(__nv_bfloat162*)(op0 + nt * 8 + cq) =
            __float22bfloat162_rn(make_float2(o[nt][0] * i0, o[nt][1] * i0));
        *(__nv_bfloat162*)(op1 + nt * 8 + cq) =
            __float22bfloat162_rn(make_float2(o[nt][2] * i1, o[nt][3] * i1));
    }
}

// ---------------------------------------------------------------------------
// Launch
// ---------------------------------------------------------------------------
extern "C" void kernel_launch(void* const* d_in, const int* in_sizes, int n_in,
                              void* d_out, int out_size) {
    const float* x      = (const float*)d_in[0];
    const float* n1_g   = (const float*)d_in[4];
    const float* n1_b   = (const float*)d_in[5];
    const float* qkv_w  = (const float*)d_in[6];
    const float* qkv_b  = (const float*)d_in[7];
    const float* proj_w = (const float*)d_in[8];
    const float* proj_b = (const float*)d_in[9];
    const float* pp_w   = (const float*)d_in[10];
    const float* pp_b   = (const float*)d_in[11];
    const float* p1_g   = (const float*)d_in[12];
    const float* p1_b   = (const float*)d_in[13];
    const float* p1_w   = (const float*)d_in[14];
    const float* p1_bi  = (const float*)d_in[15];
    const float* p2_g   = (const float*)d_in[16];
    const float* p2_b   = (const float*)d_in[17];
    const float* p2_w   = (const float*)d_in[18];
    const float* p2_bi  = (const float*)d_in[19];
    const float* p3_g   = (const float*)d_in[20];
    const float* p3_b   = (const float*)d_in[21];
    const float* p3_w   = (const float*)d_in[22];
    const float* p3_bi  = (const float*)d_in[23];
    const float* n2_g   = (const float*)d_in[24];
    const float* n2_b   = (const float*)d_in[25];
    const float* fc1_w  = (const float*)d_in[26];
    const float* fc1_b  = (const float*)d_in[27];
    const float* fc2_w  = (const float*)d_in[28];
    const float* fc2_b  = (const float*)d_in[29];
    float* out = (float*)d_out;

    __nv_bfloat16 *xw, *qkv, *attn, *ln2, *hid;
    __nv_bfloat16 *wt_qkv, *wt_proj, *wt_fc1, *wt_fc2;
    cudaGetSymbolAddress((void**)&xw,   gb_xw);
    cudaGetSymbolAddress((void**)&qkv,  gb_qkv);
    cudaGetSymbolAddress((void**)&attn, gb_attn);
    cudaGetSymbolAddress((void**)&ln2,  gb_ln2);
    cudaGetSymbolAddress((void**)&hid,  gb_hid);
    cudaGetSymbolAddress((void**)&wt_qkv,  gb_wt_qkv);
    cudaGetSymbolAddress((void**)&wt_proj, gb_wt_proj);
    cudaGetSymbolAddress((void**)&wt_fc1,  gb_wt_fc1);
    cudaGetSymbolAddress((void**)&wt_fc2,  gb_wt_fc2);

    static bool attr_set = false;
    if (!attr_set) {
        cudaFuncSetAttribute(attn_kernel, cudaFuncAttributeMaxDynamicSharedMemorySize,
                             ATTN_SMEM);
        cudaFuncSetAttribute(gemm_proj_ln, cudaFuncAttributeMaxDynamicSharedMemorySize,
                             PROJ_SMEM);
        cudaFuncSetAttribute(gemm_k192_multi<0>, cudaFuncAttributeMaxDynamicSharedMemorySize,
                             KM_SMEM);
        cudaFuncSetAttribute(gemm_k192_multi<1>, cudaFuncAttributeMaxDynamicSharedMemorySize,
                             KM_SMEM);
        cudaFuncSetAttribute(gemm_fc2, cudaFuncAttributeMaxDynamicSharedMemorySize,
                             FC2_SMEM);
        attr_set = true;
    }

    // 0. weight transposes
    transpose_all<<<(TW_TOTAL + 255) / 256, 256>>>(qkv_w, proj_w, fc1_w, fc2_w);

    // 1. bias table with inline position-MLP
    bias_build<<<(4 * HEADS * NWIN * NWIN + 255) / 256, 256>>>(
        pp_w, pp_b, p1_g, p1_b, p1_w, p1_bi,
        p2_g, p2_b, p2_w, p2_bi, p3_g, p3_b, p3_w, p3_bi);

    // 2. LN1 + shift + window partition -> bf16
    ln1_kernel<<<MROWS / 8, 256>>>(x, xw, n1_g, n1_b);

    // 3. QKV GEMM (multi-N, A resident) -> bf16, Q pre-scaled
    gemm_k192_multi<0><<<MROWS / 128, 256, KM_SMEM>>>(xw, wt_qkv, qkv_b, qkv, 576);

    // 4. tensor-core attention (24 warps/CTA) -> bf16
    attn_kernel<<<NWINDOWS, 768, ATTN_SMEM>>>(qkv, attn);

    // 5. proj + scatter + residual + LN2 (fused)
    gemm_proj_ln<<<MROWS / 128, 256, PROJ_SMEM>>>(attn, wt_proj, proj_b, x, out, ln2, n2_g, n2_b);

    // 6. FC1 + GELU (multi-N, A resident) -> bf16
    gemm_k192_multi<1><<<MROWS / 128, 256, KM_SMEM>>>(ln2, wt_fc1, fc1_b, hid, HIDDEN);

    // 7. FC2 + residual -> fp32 out (3-stage pipeline, K=768)
    gemm_fc2<<<dim3(CC / 64, MROWS / 128), 256, FC2_SMEM>>>(hid, wt_fc2, fc2_b, out, out);
}

// round 17
// speedup vs baseline: 1.0353x; 1.0086x over previous
#include <cuda_runtime.h>
#include <cuda_bf16.h>
#include <math.h>
#include <stdint.h>

// ---------------------------------------------------------------------------
// Problem constants
// ---------------------------------------------------------------------------
#define BATCH   8
#define HH      128
#define WW_     128
#define LL      (HH*WW_)
#define CC      192
#define HEADS   6
#define HD      32
#define WS      8
#define NWIN    64
#define SHIFT   4
#define HIDDEN  768
#define MROWS   (BATCH*LL)                 // 131072
#define NWINDOWS (BATCH*(HH/WS)*(WW_/WS))  // 2048
#define POS_DIM 12
#define QSCALE  0.17677669529663687f

// ---------------------------------------------------------------------------
// Device scratch
// ---------------------------------------------------------------------------
__device__ __nv_bfloat16 gb_xw[(size_t)MROWS * CC];
__device__ __nv_bfloat16 gb_qkv[(size_t)MROWS * 3 * CC];
__device__ __nv_bfloat16 gb_ln2[(size_t)MROWS * CC];
__device__ __nv_bfloat16 gb_hid[(size_t)MROWS * HIDDEN];
__device__ float g_bias[4 * HEADS * NWIN * NWIN];
__device__ __nv_bfloat16 gb_wt_qkv[3 * CC * CC];
__device__ __nv_bfloat16 gb_wt_proj[CC * CC];
__device__ __nv_bfloat16 gb_wt_fc1[HIDDEN * CC];
__device__ __nv_bfloat16 gb_wt_fc2[CC * HIDDEN];

// ---------------------------------------------------------------------------
// Helpers
// ---------------------------------------------------------------------------
__device__ __forceinline__ uint32_t smem_u32(const void* p) {
    uint32_t a;
    asm("{ .reg .u64 t; cvta.to.shared.u64 t, %1; cvt.u32.u64 %0, t; }" : "=r"(a) : "l"(p));
    return a;
}
__device__ __forceinline__ void cpasync16(uint32_t s, const void* g) {
    asm volatile("cp.async.cg.shared.global [%0], [%1], 16;" :: "r"(s), "l"(g));
}
__device__ __forceinline__ void cp_commit() {
    asm volatile("cp.async.commit_group;" ::: "memory");
}
__device__ __forceinline__ void cp_wait1() {
    asm volatile("cp.async.wait_group 1;" ::: "memory");
}
__device__ __forceinline__ void ldsm_x4(uint32_t addr, uint32_t* r) {
    asm volatile("ldmatrix.sync.aligned.m8n8.x4.shared.b16 {%0,%1,%2,%3}, [%4];"
                 : "=r"(r[0]), "=r"(r[1]), "=r"(r[2]), "=r"(r[3]) : "r"(addr));
}
__device__ __forceinline__ void mma_bf16(float* d, const uint32_t* a, const uint32_t* b) {
    asm volatile(
        "mma.sync.aligned.m16n8k16.row.col.f32.bf16.bf16.f32 "
        "{%0,%1,%2,%3}, {%4,%5,%6,%7}, {%8,%9}, {%0,%1,%2,%3};"
        : "+f"(d[0]), "+f"(d[1]), "+f"(d[2]), "+f"(d[3])
        : "r"(a[0]), "r"(a[1]), "r"(a[2]), "r"(a[3]), "r"(b[0]), "r"(b[1]));
}
__device__ __forceinline__ uint32_t packbf2(float x, float y) {
    __nv_bfloat162 t = __float22bfloat162_rn(make_float2(x, y));
    return *(uint32_t*)&t;
}
__device__ __forceinline__ float gelu_exact(float x) {
    return 0.5f * x * (1.0f + erff(x * 0.7071067811865476f));
}

// ---------------------------------------------------------------------------
// Combined weight transpose
// ---------------------------------------------------------------------------
#define TW_QKV (3*CC*CC)
#define TW_PROJ (CC*CC)
#define TW_FC1 (CC*HIDDEN)
#define TW_FC2 (HIDDEN*CC)
#define TW_TOTAL (TW_QKV + TW_PROJ + TW_FC1 + TW_FC2)

__global__ void transpose_all(const float* __restrict__ qkv_w, const float* __restrict__ proj_w,
                              const float* __restrict__ fc1_w, const float* __restrict__ fc2_w) {
    int i = blockIdx.x * 256 + threadIdx.x;
    if (i >= TW_TOTAL) return;
    const float* w; __nv_bfloat16* wt; int K, N, off;
    if (i < TW_QKV) { w = qkv_w; wt = gb_wt_qkv; K = CC; N = 3 * CC; off = i; }
    else if (i < TW_QKV + TW_PROJ) { w = proj_w; wt = gb_wt_proj; K = CC; N = CC; off = i - TW_QKV; }
    else if (i < TW_QKV + TW_PROJ + TW_FC1) { w = fc1_w; wt = gb_wt_fc1; K = CC; N = HIDDEN; off = i - TW_QKV - TW_PROJ; }
    else { w = fc2_w; wt = gb_wt_fc2; K = HIDDEN; N = CC; off = i - TW_QKV - TW_PROJ - TW_FC1; }
    int k = off / N, n = off % N;
    wt[(size_t)n * K + k] = __float2bfloat16(w[off]);
}

// ---------------------------------------------------------------------------
// Bias table with inline position-MLP
// ---------------------------------------------------------------------------
__device__ __forceinline__ void ln_relu12(const float* p, float* q,
                                          const float* g, const float* b) {
    float s = 0.f, s2 = 0.f;
#pragma unroll
    for (int i = 0; i < POS_DIM; i++) { s += p[i]; s2 += p[i] * p[i]; }
    float mu = s / 12.0f;
    float var = s2 / 12.0f - mu * mu;
    float rs = rsqrtf(var + 1e-5f);
#pragma unroll
    for (int i = 0; i < POS_DIM; i++) q[i] = fmaxf((p[i] - mu) * rs * g[i] + b[i], 0.0f);
}

__global__ void bias_build(
    const float* __restrict__ pp_w, const float* __restrict__ pp_b,
    const float* __restrict__ p1_g, const float* __restrict__ p1_b,
    const float* __restrict__ p1_w, const float* __restrict__ p1_bias,
    const float* __restrict__ p2_g, const float* __restrict__ p2_b,
    const float* __restrict__ p2_w, const float* __restrict__ p2_bias,
    const float* __restrict__ p3_g, const float* __restrict__ p3_b,
    const float* __restrict__ p3_w, const float* __restrict__ p3_bias) {
    int idx = blockIdx.x * 256 + threadIdx.x;
    if (idx >= 4 * HEADS * NWIN * NWIN) return;
    int j = idx & 63;
    int r = (idx >> 6) & 63;
    int h = (idx >> 12) % HEADS;
    int t = idx / (HEADS * NWIN * NWIN);
    int ry = r >> 3, rx = r & 7, jy = j >> 3, jx = j & 7;

    float bh = (float)(ry - jy), bw = (float)(rx - jx);
    float p[POS_DIM], q[POS_DIM];
#pragma unroll
    for (int k = 0; k < POS_DIM; k++) p[k] = bh * pp_w[k] + bw * pp_w[POS_DIM + k] + pp_b[k];
    ln_relu12(p, q, p1_g, p1_b);
#pragma unroll
    for (int k = 0; k < POS_DIM; k++) {
        float s = p1_bias[k];
#pragma unroll
        for (int i = 0; i < POS_DIM; i++) s += q[i] * p1_w[i * POS_DIM + k];
        p[k] = s;
    }
    ln_relu12(p, q, p2_g, p2_b);
#pragma unroll
    for (int k = 0; k < POS_DIM; k++) {
        float s = p2_bias[k];
#pragma unroll
        for (int i = 0; i < POS_DIM; i++) s += q[i] * p2_w[i * POS_DIM + k];
        p[k] = s;
    }
    ln_relu12(p, q, p3_g, p3_b);
    float bias = p3_bias[h];
#pragma unroll
    for (int i = 0; i < POS_DIM; i++) bias += q[i] * p3_w[i * HEADS + h];

    int lhr = (t & 2) ? (ry < (WS - SHIFT) ? 1 : 2) : 0;
    int lhj = (t & 2) ? (jy < (WS - SHIFT) ? 1 : 2) : 0;
    int lwr = (t & 1) ? (rx < (WS - SHIFT) ? 1 : 2) : 0;
    int lwj = (t & 1) ? (jx < (WS - SHIFT) ? 1 : 2) : 0;
    if (lhr != lhj || lwr != lwj) bias -= 100.0f;
    g_bias[idx] = bias;
}

// ---------------------------------------------------------------------------
// LayerNorm1: warp per row, fp32 in -> bf16 out, shift+window gather
// ---------------------------------------------------------------------------
__global__ void __launch_bounds__(256) ln1_kernel(
    const float* __restrict__ in, __nv_bfloat16* __restrict__ out,
    const float* __restrict__ gamma, const float* __restrict__ beta) {
    int warp = threadIdx.x >> 5, lane = threadIdx.x & 31;
    int row = blockIdx.x * 8 + warp;
    int bb = row >> 14, rem = row & 16383;
    int win = rem >> 6, r = rem & 63;
    int wy = win >> 4, wx = win & 15, ry = r >> 3, rx = r & 7;
    int hh = (wy * WS + ry + SHIFT) & 127;
    int ww = (wx * WS + rx + SHIFT) & 127;
    size_t src = (size_t)bb * LL + hh * WW_ + ww;

    const float* p = in + src * CC;
    float v[6], s = 0.f, s2 = 0.f;
#pragma unroll
    for (int k = 0; k < 6; k++) { v[k] = p[lane + 32 * k]; s += v[k]; s2 += v[k] * v[k]; }
#pragma unroll
    for (int o = 16; o > 0; o >>= 1) {
        s += __shfl_xor_sync(0xFFFFFFFFu, s, o);
        s2 += __shfl_xor_sync(0xFFFFFFFFu, s2, o);
    }
    float mu = s * (1.0f / 192.0f);
    float rs = rsqrtf(s2 * (1.0f / 192.0f) - mu * mu + 1e-5f);
    __nv_bfloat16* q = out + (size_t)row * CC;
#pragma unroll
    for (int k = 0; k < 6; k++) {
        int c = lane + 32 * k;
        q[c] = __float2bfloat16((v[k] - mu) * rs * gamma[c] + beta[c]);
    }
}

#define CH_PER_BUF (192 * 8)
#define A_CHB  (128 * 8)
#define B_CHB  (64 * 8)
#define ABYTES (3 * A_CHB * 16)
#define BBYTES (3 * B_CHB * 16)
#define KM_SMEM (ABYTES + 2 * BBYTES)

// ---------------------------------------------------------------------------
// K=192 multi-N GEMM: A resident, B double-buffered.
// EPI 0: +bias, Q-scale cols<192 -> bf16   1: gelu(+bias) -> bf16
// ---------------------------------------------------------------------------
template <int EPI>
__global__ void __launch_bounds__(256) gemm_k192_multi(
    const __nv_bfloat16* __restrict__ A, const __nv_bfloat16* __restrict__ BT,
    const float* __restrict__ bias, __nv_bfloat16* __restrict__ out, int NOUT) {
    extern __shared__ __align__(16) uint4 kmsq[];
    uint32_t sbase = smem_u32(kmsq);
    int tid = threadIdx.x;
    int wid = tid >> 5, lane = tid & 31;
    int wm = wid & 3, wn = wid >> 2;
    int m0 = blockIdx.x * 128;
    const int NT = NOUT >> 6;
    const __nv_bfloat16* Ab = A + (size_t)m0 * CC;

    int a_row = tid >> 1;
    int a_ch0 = (tid & 1) * 4;
    int b_row = tid >> 2;
    int b_ch0 = (tid & 3) * 2;

    int l15 = lane & 15, lhi = lane >> 4;
    int a_lrow = wm * 32 + l15;
    int a_sw = l15 & 7;
    int b_lrow = wn * 32 + (lhi << 3) + (lane & 7);
    int b_sw = lane & 7;
    int b_chlo = (lane >> 3) & 1;

#pragma unroll
    for (int kc = 0; kc < 3; kc++) {
        uint32_t dst = sbase + kc * A_CHB * 16;
        int k0 = kc << 6;
#pragma unroll
        for (int i = 0; i < 4; i++) {
            int ch = a_ch0 + i;
            cpasync16(dst + (a_row * 8 + (ch ^ (a_row & 7))) * 16,
                      Ab + (size_t)a_row * CC + k0 + ch * 8);
        }
    }
    {
        const __nv_bfloat16* Bb = BT;
#pragma unroll
        for (int kc = 0; kc < 3; kc++) {
            uint32_t dst = sbase + ABYTES + kc * B_CHB * 16;
            int k0 = kc << 6;
#pragma unroll
            for (int i = 0; i < 2; i++) {
                int ch = b_ch0 + i;
                cpasync16(dst + (b_row * 8 + (ch ^ (b_row & 7))) * 16,
                          Bb + (size_t)b_row * CC + k0 + ch * 8);
            }
        }
        cp_commit();
    }
    if (NT > 1) {
        const __nv_bfloat16* Bb = BT + (size_t)64 * CC;
#pragma unroll
        for (int kc = 0; kc < 3; kc++) {
            uint32_t dst = sbase + ABYTES + BBYTES + kc * B_CHB * 16;
            int k0 = kc << 6;
#pragma unroll
            for (int i = 0; i < 2; i++) {
                int ch = b_ch0 + i;
                cpasync16(dst + (b_row * 8 + (ch ^ (b_row & 7))) * 16,
                          Bb + (size_t)b_row * CC + k0 + ch * 8);
            }
        }
    }
    cp_commit();

    for (int nt = 0; nt < NT; nt++) {
        cp_wait1();
        __syncthreads();

        float acc[2][4][4];
#pragma unroll
        for (int i = 0; i < 2; i++)
#pragma unroll
            for (int j = 0; j < 4; j++)
#pragma unroll
                for (int k = 0; k < 4; k++) acc[i][j][k] = 0.f;

        uint32_t bbase = sbase + ABYTES + (nt & 1) * BBYTES;
#pragma unroll
        for (int kc = 0; kc < 3; kc++) {
            uint32_t abuf = sbase + kc * A_CHB * 16;
            uint32_t bbuf = bbase + kc * B_CHB * 16;
#pragma unroll
            for (int ks = 0; ks < 4; ks++) {
                uint32_t a[2][4], b[2][4];
                int achk = 2 * ks + lhi;
#pragma unroll
                for (int mt = 0; mt < 2; mt++) {
                    uint32_t idx = (a_lrow + mt * 16) * 8 + (achk ^ a_sw);
                    ldsm_x4(abuf + idx * 16, a[mt]);
                }
                int bchk = 2 * ks + b_chlo;
#pragma unroll
                for (int nt16 = 0; nt16 < 2; nt16++) {
                    uint32_t idx = (b_lrow + nt16 * 16) * 8 + (bchk ^ b_sw);
                    ldsm_x4(bbuf + idx * 16, b[nt16]);
                }
#pragma unroll
                for (int mt = 0; mt < 2; mt++) {
#pragma unroll
                    for (int nt16 = 0; nt16 < 2; nt16++) {
                        mma_bf16(acc[mt][nt16 * 2 + 0], a[mt], &b[nt16][0]);
                        mma_bf16(acc[mt][nt16 * 2 + 1], a[mt], &b[nt16][2]);
                    }
                }
            }
        }
        __syncthreads();

        if (nt + 2 < NT) {
            const __nv_bfloat16* Bb = BT + (size_t)(nt + 2) * 64 * CC;
            uint32_t dst0 = sbase + ABYTES + (nt & 1) * BBYTES;
#pragma unroll
            for (int kc = 0; kc < 3; kc++) {
                uint32_t dst = dst0 + kc * B_CHB * 16;
                int k0 = kc << 6;
#pragma unroll
                for (int i = 0; i < 2; i++) {
                    int ch = b_ch0 + i;
                    cpasync16(dst + (b_row * 8 + (ch ^ (b_row & 7))) * 16,
                              Bb + (size_t)b_row * CC + k0 + ch * 8);
                }
            }
        }
        cp_commit();

        int n0 = nt * 64;
#pragma unroll
        for (int mt = 0; mt < 2; mt++) {
            int g0 = m0 + wm * 32 + mt * 16 + (lane >> 2);
            int g1 = g0 + 8;
            size_t ob0 = (size_t)g0 * NOUT;
            size_t ob1 = (size_t)g1 * NOUT;
#pragma unroll
            for (int ne = 0; ne < 4; ne++) {
                int col = n0 + wn * 32 + ne * 8 + 2 * (lane & 3);
                float b0 = bias[col], b1 = bias[col + 1];
                float2 v0 = make_float2(acc[mt][ne][0] + b0, acc[mt][ne][1] + b1);
                float2 v1 = make_float2(acc[mt][ne][2] + b0, acc[mt][ne][3] + b1);
                if (EPI == 0) {
                    float sc = (col < CC) ? QSCALE : 1.0f;
                    v0.x *= sc; v0.y *= sc; v1.x *= sc; v1.y *= sc;
                }
                if (EPI == 1) {
                    v0.x = gelu_exact(v0.x); v0.y = gelu_exact(v0.y);
                    v1.x = gelu_exact(v1.x); v1.y = gelu_exact(v1.y);
                }
                *(__nv_bfloat162*)(out + ob0 + col) = __float22bfloat162_rn(v0);
                *(__nv_bfloat162*)(out + ob1 + col) = __float22bfloat162_rn(v1);
            }
        }
    }
}

// ---------------------------------------------------------------------------
// FC2 GEMM (K=768): 3-stage circular pipeline. +bias +res -> fp32.
// ---------------------------------------------------------------------------
#define FC2_SMEM (3 * CH_PER_BUF * 16)

__global__ void __launch_bounds__(256) gemm_fc2(
    const __nv_bfloat16* __restrict__ A, const __nv_bfloat16* __restrict__ BT,
    const float* __restrict__ bias, const float* __restrict__ res,
    float* __restrict__ out) {
    extern __shared__ __align__(16) uint4 fsmq[];
    uint32_t sbase = smem_u32(fsmq);
    const int K = HIDDEN;
    const int NCH = K >> 6;
    int tid = threadIdx.x;
    int wid = tid >> 5, lane = tid & 31;
    int wm = wid & 3, wn = wid >> 2;
    int m0 = blockIdx.y * 128, n0 = blockIdx.x * 64;
    const __nv_bfloat16* Ab = A + (size_t)m0 * K;
    const __nv_bfloat16* Bb = BT + (size_t)n0 * K;

    float acc[2][4][4];
#pragma unroll
    for (int i = 0; i < 2; i++)
#pragma unroll
        for (int j = 0; j < 4; j++)
#pragma unroll
            for (int k = 0; k < 4; k++) acc[i][j][k] = 0.f;

    int a_row = tid >> 1;
    int a_ch0 = (tid & 1) * 4;
    int b_row = tid >> 2;
    int b_ch0 = (tid & 3) * 2;

    int l15 = lane & 15, lhi = lane >> 4;
    int a_lrow = wm * 32 + l15;
    int a_sw = l15 & 7;
    int b_lrow = 128 + wn * 32 + (lhi << 3) + (lane & 7);
    int b_sw = lane & 7;
    int b_chlo = (lane >> 3) & 1;

#pragma unroll
    for (int c = 0; c < 2; c++) {
        uint32_t dst = sbase + c * CH_PER_BUF * 16;
        int k0 = c << 6;
#pragma unroll
        for (int i = 0; i < 4; i++) {
            int ch = a_ch0 + i;
            cpasync16(dst + (a_row * 8 + (ch ^ (a_row & 7))) * 16,
                      Ab + (size_t)a_row * K + k0 + ch * 8);
        }
#pragma unroll
        for (int i = 0; i < 2; i++) {
            int ch = b_ch0 + i;
            cpasync16(dst + ((128 + b_row) * 8 + (ch ^ (b_row & 7))) * 16,
                      Bb + (size_t)b_row * K + k0 + ch * 8);
        }
        cp_commit();
    }

    int bufsel = 0;
    for (int c = 0; c < NCH; c++) {
        cp_wait1();
        __syncthreads();

        if (c + 2 < NCH) {
            int nb = bufsel + 2; if (nb >= 3) nb -= 3;
            uint32_t dst = sbase + nb * CH_PER_BUF * 16;
            int k0 = (c + 2) << 6;
#pragma unroll
            for (int i = 0; i < 4; i++) {
                int ch = a_ch0 + i;
                cpasync16(dst + (a_row * 8 + (ch ^ (a_row & 7))) * 16,
                          Ab + (size_t)a_row * K + k0 + ch * 8);
            }
#pragma unroll
            for (int i = 0; i < 2; i++) {
                int ch = b_ch0 + i;
                cpasync16(dst + ((128 + b_row) * 8 + (ch ^ (b_row & 7))) * 16,
                          Bb + (size_t)b_row * K + k0 + ch * 8);
            }
        }
        cp_commit();

        uint32_t buf = sbase + bufsel * CH_PER_BUF * 16;
#pragma unroll
        for (int ks = 0; ks < 4; ks++) {
            uint32_t a[2][4], b[2][4];
            int achk = 2 * ks + lhi;
#pragma unroll
            for (int mt = 0; mt < 2; mt++) {
                uint32_t idx = (a_lrow + mt * 16) * 8 + (achk ^ a_sw);
                ldsm_x4(buf + idx * 16, a[mt]);
            }
            int bchk = 2 * ks + b_chlo;
#pragma unroll
            for (int nt16 = 0; nt16 < 2; nt16++) {
                uint32_t idx = (b_lrow + nt16 * 16) * 8 + (bchk ^ b_sw);
                ldsm_x4(buf + idx * 16, b[nt16]);
            }
#pragma unroll
            for (int mt = 0; mt < 2; mt++) {
#pragma unroll
                for (int nt16 = 0; nt16 < 2; nt16++) {
                    mma_bf16(acc[mt][nt16 * 2 + 0], a[mt], &b[nt16][0]);
                    mma_bf16(acc[mt][nt16 * 2 + 1], a[mt], &b[nt16][2]);
                }
            }
        }
        bufsel++; if (bufsel == 3) bufsel = 0;
    }

#pragma unroll
    for (int mt = 0; mt < 2; mt++) {
        int g0 = m0 + wm * 32 + mt * 16 + (lane >> 2);
        int g1 = g0 + 8;
        size_t ob0 = (size_t)g0 * CC;
        size_t ob1 = (size_t)g1 * CC;
#pragma unroll
        for (int nt = 0; nt < 4; nt++) {
            int col = n0 + wn * 32 + nt * 8 + 2 * (lane & 3);
            float b0 = bias[col], b1 = bias[col + 1];
            float2 v0 = make_float2(acc[mt][nt][0] + b0, acc[mt][nt][1] + b1);
            float2 v1 = make_float2(acc[mt][nt][2] + b0, acc[mt][nt][3] + b1);
            float2 r0 = *(const float2*)(res + ob0 + col);
            float2 r1 = *(const float2*)(res + ob1 + col);
            v0.x += r0.x; v0.y += r0.y;
            v1.x += r1.x; v1.y += r1.y;
            *(float2*)(out + ob0 + col) = v0;
            *(float2*)(out + ob1 + col) = v1;
        }
    }
}

// ---------------------------------------------------------------------------
// FUSED attention + proj + scatter + residual + LN2. 768 threads = 24 warps.
// Warp = (head h, 16-row quarter mq). Attention exactly as round 16; then O
// written bf16 into the dead Q smem region, proj weights (staged via one
// cp.async group at kernel start) multiplied in-CTA, epilogue does scatter +
// residual + cross-warp LN2 (smem reduction over the 6 head-warps per row).
// SMEM: q/o 25.6KB + k 25.6KB + vt 27.6KB + pw 76.8KB + red 3KB = ~155KB.
// ---------------------------------------------------------------------------
#define KSTR 200
#define VSTR 72
#define OQ_OFF 0
#define KS_OFF (NWIN * KSTR)
#define VT_OFF (2 * NWIN * KSTR)
#define PW_OFF (2 * NWIN * KSTR + CC * VSTR)
#define RED_OFF (PW_OFF + CC * KSTR)
#define AP_SMEM (RED_OFF * 2 + 2 * NWIN * HEADS * 4)

__global__ void __launch_bounds__(768) attn_proj_kernel(
    const __nv_bfloat16* __restrict__ qkv, const __nv_bfloat16* __restrict__ PWt,
    const float* __restrict__ pbias, const float* __restrict__ x,
    float* __restrict__ y, __nv_bfloat16* __restrict__ ln2out,
    const float* __restrict__ n2g, const float* __restrict__ n2b) {
    extern __shared__ __nv_bfloat16 smh[];
    __nv_bfloat16* q_s = smh + OQ_OFF;      // [64][KSTR]; reused for O
    __nv_bfloat16* k_s = smh + KS_OFF;      // [64][KSTR]
    __nv_bfloat16* vt_s = smh + VT_OFF;     // [192][VSTR]
    __nv_bfloat16* pw_s = smh + PW_OFF;     // [192][KSTR]
    float* red = (float*)(smh + RED_OFF);   // [2][64][6]

    int w = blockIdx.x;
    int tid = threadIdx.x;
    int lane = tid & 31, wid = tid >> 5;
    const __nv_bfloat16* base = qkv + (size_t)w * NWIN * 576;

    // proj weights via cp.async (overlaps everything below); 6 chunks/thread
    uint32_t pwb = smem_u32(pw_s);
#pragma unroll
    for (int i = 0; i < 6; i++) {
        int idx = tid + i * 768;            // 0..4607 = 192 rows x 24 chunks
        int row = idx / 24, c = idx % 24;
        cpasync16(pwb + row * (KSTR * 2) + c * 16, PWt + (size_t)row * CC + c * 8);
    }
    cp_commit();

    // stage Q, K, V
    for (int idx = tid; idx < NWIN * 24; idx += 768) {
        int j = idx / 24, c = idx % 24;
        const __nv_bfloat16* rowp = base + (size_t)j * 576 + c * 8;
        uint4 uq = *(const uint4*)(rowp);
        *(uint4*)(q_s + j * KSTR + c * 8) = uq;
        uint4 uk = *(const uint4*)(rowp + 192);
        *(uint4*)(k_s + j * KSTR + c * 8) = uk;
        uint4 uv = *(const uint4*)(rowp + 384);
        const unsigned short* e = (const unsigned short*)&uv;
#pragma unroll
        for (int i = 0; i < 8; i++) {
            int k = (i + lane) & 7;
            *((unsigned short*)vt_s + (c * 8 + k) * VSTR + j) = e[k];
        }
    }
    __syncthreads();

    int h = wid >> 2;
    int mbase = (wid & 3) * 16;
    int winloc = w & 255;
    int wy = winloc >> 4, wx = winloc & 15;
    int type = ((wy == 15) ? 2 : 0) | ((wx == 15) ? 1 : 0);
    const float* btab = g_bias + ((size_t)(type * HEADS + h) * NWIN) * NWIN;

    int rq = lane >> 2, cq = 2 * (lane & 3);
    int l15 = lane & 15, lhi = lane >> 4;
    int brow = (lhi << 3) + (lane & 7);
    int bchlo = (lane >> 3) & 1;

    // Q fragments
    uint32_t qsm = smem_u32(q_s);
    uint32_t a[2][4];
#pragma unroll
    for (int ks = 0; ks < 2; ks++) {
        uint32_t addr = qsm + ((mbase + l15) * KSTR + h * HD + ks * 16 + lhi * 8) * 2;
        ldsm_x4(addr, a[ks]);
    }
    __syncthreads();   // all Q reads complete before O overwrites q_s

    // S = Q @ K^T
    float p[8][4];
#pragma unroll
    for (int j = 0; j < 8; j++)
#pragma unroll
        for (int k = 0; k < 4; k++) p[j][k] = 0.f;

    uint32_t ksm = smem_u32(k_s);
#pragma unroll
    for (int kg = 0; kg < 4; kg++) {
#pragma unroll
        for (int ks = 0; ks < 2; ks++) {
            uint32_t b[4];
            uint32_t addr = ksm + ((kg * 16 + brow) * KSTR + (h * 4 + ks * 2 + bchlo) * 8) * 2;
            ldsm_x4(addr, b);
            mma_bf16(p[kg * 2 + 0], a[ks], &b[0]);
            mma_bf16(p[kg * 2 + 1], a[ks], &b[2]);
        }
    }

    // bias + softmax
    float sums[2];
#pragma unroll
    for (int rl = 0; rl < 2; rl++) {
        int r = mbase + rq + rl * 8;
        const float* br_ = btab + r * NWIN;
        float m = -1e30f;
#pragma unroll
        for (int nt = 0; nt < 8; nt++) {
            float2 bv = *(const float2*)(br_ + nt * 8 + cq);
            p[nt][rl * 2 + 0] += bv.x;
            p[nt][rl * 2 + 1] += bv.y;
            m = fmaxf(m, fmaxf(p[nt][rl * 2], p[nt][rl * 2 + 1]));
        }
        m = fmaxf(m, __shfl_xor_sync(0xFFFFFFFFu, m, 1));
        m = fmaxf(m, __shfl_xor_sync(0xFFFFFFFFu, m, 2));
        float s = 0.f;
#pragma unroll
        for (int nt = 0; nt < 8; nt++) {
            float e0 = __expf(p[nt][rl * 2] - m);
            float e1 = __expf(p[nt][rl * 2 + 1] - m);
            p[nt][rl * 2] = e0; p[nt][rl * 2 + 1] = e1;
            s += e0 + e1;
        }
        s += __shfl_xor_sync(0xFFFFFFFFu, s, 1);
        s += __shfl_xor_sync(0xFFFFFFFFu, s, 2);
        sums[rl] = s;
    }

    uint32_t pa[4][4];
#pragma unroll
    for (int s4 = 0; s4 < 4; s4++) {
        pa[s4][0] = packbf2(p[2 * s4][0], p[2 * s4][1]);
        pa[s4][1] = packbf2(p[2 * s4][2], p[2 * s4][3]);
        pa[s4][2] = packbf2(p[2 * s4 + 1][0], p[2 * s4 + 1][1]);
        pa[s4][3] = packbf2(p[2 * s4 + 1][2], p[2 * s4 + 1][3]);
    }

    // O = P @ V
    float o[4][4];
#pragma unroll
    for (int j = 0; j < 4; j++)
#pragma unroll
        for (int k = 0; k < 4; k++) o[j][k] = 0.f;

    uint32_t vsm = smem_u32(vt_s);
#pragma unroll
    for (int s4 = 0; s4 < 4; s4++) {
#pragma unroll
        for (int n16 = 0; n16 < 2; n16++) {
            uint32_t b[4];
            uint32_t addr = vsm + ((h * HD + n16 * 16 + brow) * VSTR + (s4 * 2 + bchlo) * 8) * 2;
            ldsm_x4(addr, b);
            mma_bf16(o[n16 * 2 + 0], pa[s4], &b[0]);
            mma_bf16(o[n16 * 2 + 1], pa[s4], &b[2]);
        }
    }

    // normalize + store O into q_s (bf16)
    {
        float i0 = 1.0f / sums[0];
        float i1 = 1.0f / sums[1];
        int r0 = mbase + rq, r1 = r0 + 8;
#pragma unroll
        for (int nt = 0; nt < 4; nt++) {
            int col = h * HD + nt * 8 + cq;
            *(uint32_t*)(q_s + r0 * KSTR + col) = packbf2(o[nt][0] * i0, o[nt][1] * i0);
            *(uint32_t*)(q_s + r1 * KSTR + col) = packbf2(o[nt][2] * i1, o[nt][3] * i1);
        }
    }
    asm volatile("cp.async.wait_group 0;" ::: "memory");
    __syncthreads();   // O visible + proj weights ready

    // proj: warp computes rows [mbase,+16) x cols [h*32,+32); K=192
    float acc[4][4];
#pragma unroll
    for (int j = 0; j < 4; j++)
#pragma unroll
        for (int k = 0; k < 4; k++) acc[j][k] = 0.f;

    int n0 = h * 32;
#pragma unroll
    for (int ks = 0; ks < 12; ks++) {
        uint32_t av[4];
        ldsm_x4(qsm + ((mbase + l15) * KSTR + ks * 16 + lhi * 8) * 2, av);
        uint32_t b0[4], b1[4];
        ldsm_x4(pwb + ((n0 + brow) * KSTR + ks * 16 + bchlo * 8) * 2, b0);
        ldsm_x4(pwb + ((n0 + 16 + brow) * KSTR + ks * 16 + bchlo * 8) * 2, b1);
        mma_bf16(acc[0], av, &b0[0]);
        mma_bf16(acc[1], av, &b0[2]);
        mma_bf16(acc[2], av, &b1[0]);
        mma_bf16(acc[3], av, &b1[2]);
    }

    // epilogue: scatter + residual + partial LN sums
    float vv[2][4][2];
    size_t obs[2];
#pragma unroll
    for (int rl = 0; rl < 2; rl++) {
        int r = mbase + rq + rl * 8;
        int g = w * NWIN + r;
        int bb = g >> 14, rem = g & 16383;
        int win = rem >> 6, rr = rem & 63;
        int wyy = win >> 4, wxx = win & 15, ryy = rr >> 3, rxx = rr & 7;
        int hh = (wyy * WS + ryy + SHIFT) & 127;
        int ww = (wxx * WS + rxx + SHIFT) & 127;
        size_t ob = ((size_t)bb * LL + hh * WW_ + ww) * CC;
        obs[rl] = ob;

        float s = 0.f, s2 = 0.f;
#pragma unroll
        for (int nt = 0; nt < 4; nt++) {
            int col = n0 + nt * 8 + cq;
            float2 rv = *(const float2*)(x + ob + col);
            float v0 = acc[nt][rl * 2 + 0] + pbias[col] + rv.x;
            float v1 = acc[nt][rl * 2 + 1] + pbias[col + 1] + rv.y;
            *(float2*)(y + ob + col) = make_float2(v0, v1);
            s += v0 + v1;
            s2 += v0 * v0 + v1 * v1;
            vv[rl][nt][0] = v0; vv[rl][nt][1] = v1;
        }
        s += __shfl_xor_sync(0xFFFFFFFFu, s, 1);
        s2 += __shfl_xor_sync(0xFFFFFFFFu, s2, 1);
        s += __shfl_xor_sync(0xFFFFFFFFu, s, 2);
        s2 += __shfl_xor_sync(0xFFFFFFFFu, s2, 2);
        if ((lane & 3) == 0) {
            red[r * HEADS + h] = s;
            red[NWIN * HEADS + r * HEADS + h] = s2;
        }
    }
    __syncthreads();

    // LN2 finalize
#pragma unroll
    for (int rl = 0; rl < 2; rl++) {
        int r = mbase + rq + rl * 8;
        float s = 0.f, s2 = 0.f;
#pragma unroll
        for (int hh = 0; hh < HEADS; hh++) {
            s += red[r * HEADS + hh];
            s2 += red[NWIN * HEADS + r * HEADS + hh];
        }
        float mu = s * (1.0f / 192.0f);
        float rs = rsqrtf(s2 * (1.0f / 192.0f) - mu * mu + 1e-5f);
        size_t ob = obs[rl];
#pragma unroll
        for (int nt = 0; nt < 4; nt++) {
            int col = n0 + nt * 8 + cq;
            float2 gg = *(const float2*)(n2g + col);
            float2 bb2 = *(const float2*)(n2b + col);
            float o0 = (vv[rl][nt][0] - mu) * rs * gg.x + bb2.x;
            float o1 = (vv[rl][nt][1] - mu) * rs * gg.y + bb2.y;
            *(__nv_bfloat162*)(ln2out + ob + col) = __float22bfloat162_rn(make_float2(o0, o1));
        }
    }
}

// ---------------------------------------------------------------------------
// Launch
// ---------------------------------------------------------------------------
extern "C" void kernel_launch(void* const* d_in, const int* in_sizes, int n_in,
                              void* d_out, int out_size) {
    const float* x      = (const float*)d_in[0];
    const float* n1_g   = (const float*)d_in[4];
    const float* n1_b   = (const float*)d_in[5];
    const float* qkv_w  = (const float*)d_in[6];
    const float* qkv_b  = (const float*)d_in[7];
    const float* proj_w = (const float*)d_in[8];
    const float* proj_b = (const float*)d_in[9];
    const float* pp_w   = (const float*)d_in[10];
    const float* pp_b   = (const float*)d_in[11];
    const float* p1_g   = (const float*)d_in[12];
    const float* p1_b   = (const float*)d_in[13];
    const float* p1_w   = (const float*)d_in[14];
    const float* p1_bi  = (const float*)d_in[15];
    const float* p2_g   = (const float*)d_in[16];
    const float* p2_b   = (const float*)d_in[17];
    const float* p2_w   = (const float*)d_in[18];
    const float* p2_bi  = (const float*)d_in[19];
    const float* p3_g   = (const float*)d_in[20];
    const float* p3_b   = (const float*)d_in[21];
    const float* p3_w   = (const float*)d_in[22];
    const float* p3_bi  = (const float*)d_in[23];
    const float* n2_g   = (const float*)d_in[24];
    const float* n2_b   = (const float*)d_in[25];
    const float* fc1_w  = (const float*)d_in[26];
    const float* fc1_b  = (const float*)d_in[27];
    const float* fc2_w  = (const float*)d_in[28];
    const float* fc2_b  = (const float*)d_in[29];
    float* out = (float*)d_out;

    __nv_bfloat16 *xw, *qkv, *ln2, *hid;
    __nv_bfloat16 *wt_qkv, *wt_proj, *wt_fc1, *wt_fc2;
    cudaGetSymbolAddress((void**)&xw,   gb_xw);
    cudaGetSymbolAddress((void**)&qkv,  gb_qkv);
    cudaGetSymbolAddress((void**)&ln2,  gb_ln2);
    cudaGetSymbolAddress((void**)&hid,  gb_hid);
    cudaGetSymbolAddress((void**)&wt_qkv,  gb_wt_qkv);
    cudaGetSymbolAddress((void**)&wt_proj, gb_wt_proj);
    cudaGetSymbolAddress((void**)&wt_fc1,  gb_wt_fc1);
    cudaGetSymbolAddress((void**)&wt_fc2,  gb_wt_fc2);

    static bool attr_set = false;
    if (!attr_set) {
        cudaFuncSetAttribute(attn_proj_kernel, cudaFuncAttributeMaxDynamicSharedMemorySize,
                             AP_SMEM);
        cudaFuncSetAttribute(gemm_k192_multi<0>, cudaFuncAttributeMaxDynamicSharedMemorySize,
                             KM_SMEM);
        cudaFuncSetAttribute(gemm_k192_multi<1>, cudaFuncAttributeMaxDynamicSharedMemorySize,
                             KM_SMEM);
        cudaFuncSetAttribute(gemm_fc2, cudaFuncAttributeMaxDynamicSharedMemorySize,
                             FC2_SMEM);
        attr_set = true;
    }

    // 0. weight transposes
    transpose_all<<<(TW_TOTAL + 255) / 256, 256>>>(qkv_w, proj_w, fc1_w, fc2_w);

    // 1. bias table with inline position-MLP
    bias_build<<<(4 * HEADS * NWIN * NWIN + 255) / 256, 256>>>(
        pp_w, pp_b, p1_g, p1_b, p1_w, p1_bi,
        p2_g, p2_b, p2_w, p2_bi, p3_g, p3_b, p3_w, p3_bi);

    // 2. LN1 + shift + window partition -> bf16
    ln1_kernel<<<MROWS / 8, 256>>>(x, xw, n1_g, n1_b);

    // 3. QKV GEMM (multi-N, A resident) -> bf16, Q pre-scaled
    gemm_k192_multi<0><<<MROWS / 128, 256, KM_SMEM>>>(xw, wt_qkv, qkv_b, qkv, 576);

    // 4. fused attention + proj + scatter + residual + LN2
    attn_proj_kernel<<<NWINDOWS, 768, AP_SMEM>>>(qkv, wt_proj, proj_b, x, out, ln2,
                                                 n2_g, n2_b);

    // 5. FC1 + GELU (multi-N, A resident) -> bf16
    gemm_k192_multi<1><<<MROWS / 128, 256, KM_SMEM>>>(ln2, wt_fc1, fc1_b, hid, HIDDEN);

    // 6. FC2 + residual -> fp32 out (3-stage pipeline, K=768)
    gemm_fc2<<<dim3(CC / 64, MROWS / 128), 256, FC2_SMEM>>>(hid, wt_fc2, fc2_b, out, out);
}